// round 1
// baseline (speedup 1.0000x reference)
#include <cuda_runtime.h>
#include <math.h>
#include <float.h>
#include <limits.h>
#include <stdint.h>

#define BB 16
#define AA 8400
#define TT 128
#define CC 80

// ---------------- scratch (static device globals; no allocation) ----------------
__device__ float d_S[BB*AA];                    // sum_c log1mp per anchor
__device__ float d_D[BB*CC*AA];                 // (logp - log1mp), class-major
__device__ float4 d_pbox[BB*AA];                // pred boxes packed
__device__ float4 d_anchor[AA];                 // xc, yc, stride
__device__ unsigned char d_inb[BB*AA];          // in_box (any target)
__device__ unsigned int d_ibc[BB*4*AA];         // in_box&in_center bitmask, word-major
__device__ float d_iou[(size_t)BB*TT*AA];
__device__ float d_cost[(size_t)BB*TT*AA];
__device__ int   d_dynk[BB*TT];
__device__ float d_rowmax[BB*TT];
__device__ int   d_mcnt[BB*AA];
__device__ int   d_mt[BB*AA];
__device__ double d_acc[4];                     // lbox_sum, m_sum, lobj_sum, lcls_sum

__device__ __forceinline__ float bce(float x, float t) {
    return fmaxf(x, 0.f) - x * t + log1pf(expf(-fabsf(x)));
}
// jax.lax.top_k: stable — larger value first, ties -> smaller index first
__device__ __forceinline__ bool better(float k1, int i1, float k2, int i2) {
    return (k1 > k2) || (k1 == k2 && i1 < i2);
}

// ---------------- init ----------------
__global__ void k_init() {
    int i = blockIdx.x * blockDim.x + threadIdx.x;
    if (i < BB*AA) { d_mcnt[i] = 0; d_mt[i] = INT_MAX; }
    if (i < 4) d_acc[i] = 0.0;
}

__global__ void k_anchor(const float* __restrict__ grid, const float* __restrict__ str) {
    int a = blockIdx.x * blockDim.x + threadIdx.x;
    if (a >= AA) return;
    float s = str[a];
    float4 v;
    v.x = (grid[2*a] + 0.5f) * s;
    v.y = (grid[2*a+1] + 0.5f) * s;
    v.z = s; v.w = 0.f;
    d_anchor[a] = v;
}

// ---------------- pass1: per-anchor class prob terms ----------------
__global__ void k_pass1(const float* __restrict__ pred) {
    int i = blockIdx.x * blockDim.x + threadIdx.x;
    if (i >= BB*AA) return;
    int b = i / AA, a = i - b*AA;
    const float* row = pred + (size_t)i * 85;
    float4 pb; pb.x = row[0]; pb.y = row[1]; pb.z = row[2]; pb.w = row[3];
    d_pbox[i] = pb;
    float so = 1.f / (1.f + __expf(-row[4]));
    float S = 0.f;
    #pragma unroll 4
    for (int c = 0; c < CC; c++) {
        float sc = 1.f / (1.f + __expf(-row[5 + c]));
        float p  = sqrtf(so * sc);
        float lp = fmaxf(__logf(p), -100.f);
        float l1 = fmaxf(__logf(1.f - p), -100.f);
        S += l1;
        d_D[((size_t)(b*CC + c)) * AA + a] = lp - l1;
    }
    d_S[i] = S;
}

// ---------------- pass2: geometric flags ----------------
__global__ void k_pass2(const float* __restrict__ target) {
    int b = blockIdx.y;
    int a = blockIdx.x * blockDim.x + threadIdx.x;
    __shared__ float st[TT*6];
    for (int i = threadIdx.x; i < TT*6; i += blockDim.x)
        st[i] = target[(size_t)b*TT*6 + i];
    __syncthreads();
    if (a >= AA) return;
    float4 an = d_anchor[a];
    float xc = an.x, yc = an.y, r = 2.5f * an.z;
    unsigned w0=0, w1=0, w2=0, w3=0;
    bool any = false;
    for (int t = 0; t < TT; t++) {
        const float* tb = st + t*6;
        float x1 = tb[2], y1 = tb[3], x2 = tb[4], y2 = tb[5];
        float dmin = fminf(fminf(xc - x1, yc - y1), fminf(x2 - xc, y2 - yc));
        bool ib = dmin > 0.f;
        float txc = (x1 + x2) * 0.5f, tyc = (y1 + y2) * 0.5f;
        bool ic = fmaxf(fabsf(xc - txc), fabsf(yc - tyc)) < r;
        any |= (ib || ic);
        if (ib && ic) {
            unsigned bit = 1u << (t & 31);
            if (t < 32) w0 |= bit; else if (t < 64) w1 |= bit;
            else if (t < 96) w2 |= bit; else w3 |= bit;
        }
    }
    d_inb[b*AA + a] = any ? 1 : 0;
    d_ibc[(b*4 + 0)*AA + a] = w0;
    d_ibc[(b*4 + 1)*AA + a] = w1;
    d_ibc[(b*4 + 2)*AA + a] = w2;
    d_ibc[(b*4 + 3)*AA + a] = w3;
}

// ---------------- pass3: pairwise iou + cost ----------------
__global__ void k_pass3(const float* __restrict__ target) {
    int b = blockIdx.z, t = blockIdx.y;
    int a = blockIdx.x * blockDim.x + threadIdx.x;
    if (a >= AA) return;
    const float* tr = target + ((size_t)b*TT + t) * 6;
    float x1 = tr[2], y1 = tr[3], x2 = tr[4], y2 = tr[5];
    int ci = (int)tr[1];
    float area_t = fmaxf(x2 - x1, 0.f) * fmaxf(y2 - y1, 0.f);
    int ba = b*AA + a;
    float4 pb = d_pbox[ba];
    bool inb = d_inb[ba] != 0;
    unsigned w = d_ibc[(b*4 + (t >> 5))*AA + a];
    bool ibc = (w >> (t & 31)) & 1u;
    float ltx = fmaxf(x1, pb.x), lty = fmaxf(y1, pb.y);
    float rbx = fminf(x2, pb.z), rby = fminf(y2, pb.w);
    float wx = fmaxf(rbx - ltx, 0.f), wy = fmaxf(rby - lty, 0.f);
    float inter = wx * wy;
    float area_p = fmaxf(pb.z - pb.x, 0.f) * fmaxf(pb.w - pb.y, 0.f);
    float iou = inter / (area_t + area_p - inter + 1e-8f);
    iou = inb ? iou : 0.f;
    float iouc = -__logf(iou + 1e-8f);
    float clsc = -(d_S[ba] + d_D[((size_t)(b*CC + ci))*AA + a]);
    float cost = clsc + 3.0f * iouc;
    if (!ibc) cost += 100000.0f;
    if (!inb) cost += 1000000000.0f;
    size_t o = ((size_t)b*TT + t)*AA + a;
    d_iou[o] = iou;
    d_cost[o] = cost;
}

// ---------------- pass4: per-(b,t) top-k + scatter ----------------
__device__ __forceinline__ void top10_insert(float* lk, int* li, float k, int i) {
    if (!better(k, i, lk[9], li[9])) return;
    int p = 9;
    #pragma unroll
    for (int q = 9; q > 0; q--) {
        if (better(k, i, lk[q-1], li[q-1])) { lk[q] = lk[q-1]; li[q] = li[q-1]; p = q - 1; }
        else break;
    }
    lk[p] = k; li[p] = i;
}

__device__ __forceinline__ void merge_lists(float* sK, int* sI, int tid) {
    for (int step = 1; step < 128; step <<= 1) {
        __syncthreads();
        if ((tid & (2*step - 1)) == 0) {
            int o = tid*10, p = (tid + step)*10;
            int pa = 0, pb = 0;
            float ov[10]; int oi[10];
            #pragma unroll
            for (int j = 0; j < 10; j++) {
                float ka = sK[o + pa]; int ia = sI[o + pa];
                float kb = sK[p + pb]; int ib = sI[p + pb];
                if (better(ka, ia, kb, ib)) { ov[j] = ka; oi[j] = ia; pa++; }
                else                        { ov[j] = kb; oi[j] = ib; pb++; }
            }
            #pragma unroll
            for (int j = 0; j < 10; j++) { sK[o + j] = ov[j]; sI[o + j] = oi[j]; }
        }
    }
    __syncthreads();
}

__global__ void k_pass4() {
    int t = blockIdx.x, b = blockIdx.y, tid = threadIdx.x;
    int bt = b*TT + t;
    const float* irow = d_iou  + (size_t)bt * AA;
    const float* crow = d_cost + (size_t)bt * AA;
    __shared__ float sK[128*10];
    __shared__ int   sI[128*10];
    __shared__ int   s_dynk;
    float lk[10]; int li[10];

    // phase 0: top-10 iou -> dyn_k, rowmax
    #pragma unroll
    for (int j = 0; j < 10; j++) { lk[j] = -FLT_MAX; li[j] = INT_MAX; }
    for (int a = tid; a < AA; a += 128) top10_insert(lk, li, irow[a], a);
    #pragma unroll
    for (int j = 0; j < 10; j++) { sK[tid*10 + j] = lk[j]; sI[tid*10 + j] = li[j]; }
    merge_lists(sK, sI, tid);
    if (tid == 0) {
        float s = 0.f;
        #pragma unroll
        for (int j = 0; j < 10; j++) s += sK[j];
        int dk = (int)s;                 // truncation, matches astype(int32)
        if (dk < 1) dk = 1; if (dk > 10) dk = 10;
        s_dynk = dk;
        d_dynk[bt] = dk;
        d_rowmax[bt] = sK[0];
    }
    __syncthreads();

    // phase 1: top-10 of -cost -> selected anchors, scatter matches
    #pragma unroll
    for (int j = 0; j < 10; j++) { lk[j] = -FLT_MAX; li[j] = INT_MAX; }
    for (int a = tid; a < AA; a += 128) top10_insert(lk, li, -crow[a], a);
    #pragma unroll
    for (int j = 0; j < 10; j++) { sK[tid*10 + j] = lk[j]; sI[tid*10 + j] = li[j]; }
    merge_lists(sK, sI, tid);
    if (tid < 10) {
        int aa = sI[tid];
        if (tid < s_dynk && d_inb[b*AA + aa]) {
            atomicAdd(&d_mcnt[b*AA + aa], 1);
            atomicMin(&d_mt[b*AA + aa], t);
        }
    }
}

// ---------------- pass5: column ops + fused loss ----------------
__global__ void k_pass5(const float* __restrict__ pred, const float* __restrict__ target) {
    int b = blockIdx.y;
    int a = blockIdx.x * blockDim.x + threadIdx.x;
    int tid = threadIdx.x;
    __shared__ float s_rm[TT];
    if (tid < TT) s_rm[tid] = d_rowmax[b*TT + tid];
    __syncthreads();

    float t_lbox = 0.f, t_m = 0.f, t_lobj = 0.f, t_lcls = 0.f;
    if (a < AA) {
        int ba = b*AA + a;
        size_t base = (size_t)b*TT*AA + a;
        float piou = 0.f;
        float bestc = FLT_MAX; int bestt = 0;
        for (int t = 0; t < TT; t++) {
            float iv = d_iou[base + (size_t)t*AA];
            piou = fmaxf(piou, iv / (s_rm[t] + 1e-8f));
            float cv = d_cost[base + (size_t)t*AA];
            if (cv < bestc) { bestc = cv; bestt = t; }   // first min, matches argmin
        }
        bool inb = d_inb[ba] != 0;
        float objt = inb ? fminf(fmaxf(piou, 0.f), 1.f) : 0.f;
        const float* prow = pred + (size_t)ba * 85;
        t_lobj = bce(prow[4], objt);

        int cnt = d_mcnt[ba];
        int tp = -1;
        if (cnt == 1) tp = d_mt[ba];
        else if (cnt > 1) tp = bestt;
        if (tp >= 0) {
            t_m = 1.f;
            const float* tr = target + ((size_t)b*TT + tp) * 6;
            float tx1 = tr[2], ty1 = tr[3], tx2 = tr[4], ty2 = tr[5];
            int ci = (int)tr[1];
            float4 pb = d_pbox[ba];
            // CIoU
            float ltx = fmaxf(pb.x, tx1), lty = fmaxf(pb.y, ty1);
            float rbx = fminf(pb.z, tx2), rby = fminf(pb.w, ty2);
            float wx = fmaxf(rbx - ltx, 0.f), wy = fmaxf(rby - lty, 0.f);
            float inter = wx * wy;
            float wp = pb.z - pb.x, hp = pb.w - pb.y;
            float wt = tx2 - tx1, ht = ty2 - ty1;
            float iou = inter / (wp*hp + wt*ht - inter + 1e-8f);
            float cw = fmaxf(pb.z, tx2) - fminf(pb.x, tx1);
            float ch = fmaxf(pb.w, ty2) - fminf(pb.y, ty1);
            float c2 = cw*cw + ch*ch + 1e-8f;
            float dx = pb.x + pb.z - (tx1 + tx2);
            float dy = pb.y + pb.w - (ty1 + ty2);
            float rho2 = (dx*dx + dy*dy) * 0.25f;
            const float k4pi2 = (float)(4.0 / (M_PI * M_PI));
            float dv = atanf(wt / (ht + 1e-8f)) - atanf(wp / (hp + 1e-8f));
            float v = k4pi2 * dv * dv;
            float alpha = v / (1.f - iou + v + 1e-8f);
            float ciou = iou - rho2 / c2 - alpha * v;
            t_lbox = 1.f - ciou;
            float s = 0.f;
            for (int c = 0; c < CC; c++)
                s += bce(prow[5 + c], (c == ci) ? 1.f : 0.f);
            t_lcls = s * (1.0f / CC);
        }
    }

    // block reduction of 4 partials
    __shared__ float red[4*256];
    red[tid] = t_lbox; red[256 + tid] = t_m;
    red[512 + tid] = t_lobj; red[768 + tid] = t_lcls;
    __syncthreads();
    for (int s = 128; s > 0; s >>= 1) {
        if (tid < s) {
            red[tid]       += red[tid + s];
            red[256 + tid] += red[256 + tid + s];
            red[512 + tid] += red[512 + tid + s];
            red[768 + tid] += red[768 + tid + s];
        }
        __syncthreads();
    }
    if (tid == 0) {
        atomicAdd(&d_acc[0], (double)red[0]);
        atomicAdd(&d_acc[1], (double)red[256]);
        atomicAdd(&d_acc[2], (double)red[512]);
        atomicAdd(&d_acc[3], (double)red[768]);
    }
}

// ---------------- finalize ----------------
__global__ void k_final(float* out, int n) {
    double nm = d_acc[1];
    if (nm < 1.0) nm = 1.0;
    float lbox = (float)(0.05 * d_acc[0] / nm);
    float lobj = (float)(d_acc[2] / (double)(BB*AA));
    float lcls = (float)(0.5 * d_acc[3] / nm);
    float loss = lbox + lobj + lcls;
    if (n > 0) out[0] = loss;
    if (n > 1) out[1] = lbox;
    if (n > 2) out[2] = lobj;
    if (n > 3) out[3] = lcls;
}

// ---------------- launch ----------------
extern "C" void kernel_launch(void* const* d_in, const int* in_sizes, int n_in,
                              void* d_out, int out_size) {
    const float *pred = nullptr, *target = nullptr, *grid = nullptr, *stridem = nullptr;
    for (int i = 0; i < n_in; i++) {
        switch (in_sizes[i]) {
            case BB*AA*85:  pred    = (const float*)d_in[i]; break;
            case BB*TT*6:   target  = (const float*)d_in[i]; break;
            case AA*2:      grid    = (const float*)d_in[i]; break;
            case AA:        stridem = (const float*)d_in[i]; break;
            default: break;
        }
    }
    // positional fallback
    if (!pred    && n_in > 0) pred    = (const float*)d_in[0];
    if (!target  && n_in > 1) target  = (const float*)d_in[1];
    if (!grid    && n_in > 2) grid    = (const float*)d_in[2];
    if (!stridem && n_in > 3) stridem = (const float*)d_in[3];
    float* out = (float*)d_out;

    k_init<<<(BB*AA + 255)/256, 256>>>();
    k_anchor<<<(AA + 255)/256, 256>>>(grid, stridem);
    k_pass1<<<(BB*AA + 127)/128, 128>>>(pred);
    {
        dim3 g((AA + 255)/256, BB);
        k_pass2<<<g, 256>>>(target);
    }
    {
        dim3 g((AA + 255)/256, TT, BB);
        k_pass3<<<g, 256>>>(target);
    }
    {
        dim3 g(TT, BB);
        k_pass4<<<g, 128>>>();
    }
    {
        dim3 g((AA + 255)/256, BB);
        k_pass5<<<g, 256>>>(pred, target);
    }
    k_final<<<1, 1>>>(out, out_size);
}

// round 2
// speedup vs baseline: 1.0165x; 1.0165x over previous
#include <cuda_runtime.h>
#include <math.h>
#include <float.h>
#include <limits.h>
#include <stdint.h>

#define BB 16
#define AA 8400
#define TT 128
#define CC 80

// ---------------- scratch (static device globals; no allocation) ----------------
__device__ float d_S[BB*AA];                    // sum_c log1mp per anchor
__device__ float d_D[BB*CC*AA];                 // (logp - log1mp), class-major
__device__ float4 d_pbox[BB*AA];                // pred boxes packed
__device__ float4 d_anchor[AA];                 // xc, yc, stride
__device__ unsigned char d_inb[BB*AA];          // in_box (any target)
__device__ unsigned int d_ibc[BB*4*AA];         // in_box&in_center bitmask, word-major
__device__ float d_iou[(size_t)BB*TT*AA];
__device__ float d_cost[(size_t)BB*TT*AA];
__device__ int   d_dynk[BB*TT];
__device__ float d_rowmax[BB*TT];
__device__ int   d_mcnt[BB*AA];
__device__ int   d_mt[BB*AA];
__device__ double d_acc[4];                     // lbox_sum, m_sum, lobj_sum, lcls_sum

__device__ __forceinline__ float bce(float x, float t) {
    return fmaxf(x, 0.f) - x * t + log1pf(expf(-fabsf(x)));
}
// jax.lax.top_k: stable — larger value first, ties -> smaller index first
__device__ __forceinline__ bool better(float k1, int i1, float k2, int i2) {
    return (k1 > k2) || (k1 == k2 && i1 < i2);
}

// ---------------- init ----------------
__global__ void k_init() {
    int i = blockIdx.x * blockDim.x + threadIdx.x;
    if (i < BB*AA) { d_mcnt[i] = 0; d_mt[i] = INT_MAX; }
    if (i < 4) d_acc[i] = 0.0;
}

__global__ void k_anchor(const float* __restrict__ grid, const float* __restrict__ str) {
    int a = blockIdx.x * blockDim.x + threadIdx.x;
    if (a >= AA) return;
    float s = str[a];
    float4 v;
    v.x = (grid[2*a] + 0.5f) * s;
    v.y = (grid[2*a+1] + 0.5f) * s;
    v.z = s; v.w = 0.f;
    d_anchor[a] = v;
}

// ---------------- pass1: per-anchor class prob terms ----------------
__global__ void k_pass1(const float* __restrict__ pred) {
    int i = blockIdx.x * blockDim.x + threadIdx.x;
    if (i >= BB*AA) return;
    int b = i / AA, a = i - b*AA;
    const float* row = pred + (size_t)i * 85;
    float4 pb; pb.x = row[0]; pb.y = row[1]; pb.z = row[2]; pb.w = row[3];
    d_pbox[i] = pb;
    float so = 1.f / (1.f + __expf(-row[4]));
    float S = 0.f;
    #pragma unroll 4
    for (int c = 0; c < CC; c++) {
        float sc = 1.f / (1.f + __expf(-row[5 + c]));
        float p  = sqrtf(so * sc);
        float lp = fmaxf(__logf(p), -100.f);
        float l1 = fmaxf(__logf(1.f - p), -100.f);
        S += l1;
        d_D[((size_t)(b*CC + c)) * AA + a] = lp - l1;
    }
    d_S[i] = S;
}

// ---------------- pass2: geometric flags ----------------
__global__ void k_pass2(const float* __restrict__ target) {
    int b = blockIdx.y;
    int a = blockIdx.x * blockDim.x + threadIdx.x;
    __shared__ float st[TT*6];
    for (int i = threadIdx.x; i < TT*6; i += blockDim.x)
        st[i] = target[(size_t)b*TT*6 + i];
    __syncthreads();
    if (a >= AA) return;
    float4 an = d_anchor[a];
    float xc = an.x, yc = an.y, r = 2.5f * an.z;
    unsigned w0=0, w1=0, w2=0, w3=0;
    bool any = false;
    for (int t = 0; t < TT; t++) {
        const float* tb = st + t*6;
        float x1 = tb[2], y1 = tb[3], x2 = tb[4], y2 = tb[5];
        float dmin = fminf(fminf(xc - x1, yc - y1), fminf(x2 - xc, y2 - yc));
        bool ib = dmin > 0.f;
        float txc = (x1 + x2) * 0.5f, tyc = (y1 + y2) * 0.5f;
        bool ic = fmaxf(fabsf(xc - txc), fabsf(yc - tyc)) < r;
        any |= (ib || ic);
        if (ib && ic) {
            unsigned bit = 1u << (t & 31);
            if (t < 32) w0 |= bit; else if (t < 64) w1 |= bit;
            else if (t < 96) w2 |= bit; else w3 |= bit;
        }
    }
    d_inb[b*AA + a] = any ? 1 : 0;
    d_ibc[(b*4 + 0)*AA + a] = w0;
    d_ibc[(b*4 + 1)*AA + a] = w1;
    d_ibc[(b*4 + 2)*AA + a] = w2;
    d_ibc[(b*4 + 3)*AA + a] = w3;
}

// ---------------- pass3: pairwise iou + cost ----------------
__global__ void k_pass3(const float* __restrict__ target) {
    int b = blockIdx.z, t = blockIdx.y;
    int a = blockIdx.x * blockDim.x + threadIdx.x;
    if (a >= AA) return;
    const float* tr = target + ((size_t)b*TT + t) * 6;
    float x1 = tr[2], y1 = tr[3], x2 = tr[4], y2 = tr[5];
    int ci = (int)tr[1];
    float area_t = fmaxf(x2 - x1, 0.f) * fmaxf(y2 - y1, 0.f);
    int ba = b*AA + a;
    float4 pb = d_pbox[ba];
    bool inb = d_inb[ba] != 0;
    unsigned w = d_ibc[(b*4 + (t >> 5))*AA + a];
    bool ibc = (w >> (t & 31)) & 1u;
    float ltx = fmaxf(x1, pb.x), lty = fmaxf(y1, pb.y);
    float rbx = fminf(x2, pb.z), rby = fminf(y2, pb.w);
    float wx = fmaxf(rbx - ltx, 0.f), wy = fmaxf(rby - lty, 0.f);
    float inter = wx * wy;
    float area_p = fmaxf(pb.z - pb.x, 0.f) * fmaxf(pb.w - pb.y, 0.f);
    float iou = inter / (area_t + area_p - inter + 1e-8f);
    iou = inb ? iou : 0.f;
    float iouc = -__logf(iou + 1e-8f);
    float clsc = -(d_S[ba] + d_D[((size_t)(b*CC + ci))*AA + a]);
    float cost = clsc + 3.0f * iouc;
    if (!ibc) cost += 100000.0f;
    if (!inb) cost += 1000000000.0f;
    size_t o = ((size_t)b*TT + t)*AA + a;
    d_iou[o] = iou;
    d_cost[o] = cost;
}

// ---------------- pass4: per-(b,t) top-k + scatter ----------------
__device__ __forceinline__ void top10_insert(float* lk, int* li, float k, int i) {
    if (!better(k, i, lk[9], li[9])) return;
    int p = 9;
    #pragma unroll
    for (int q = 9; q > 0; q--) {
        if (better(k, i, lk[q-1], li[q-1])) { lk[q] = lk[q-1]; li[q] = li[q-1]; p = q - 1; }
        else break;
    }
    lk[p] = k; li[p] = i;
}

__device__ __forceinline__ void merge_lists(float* sK, int* sI, int tid) {
    for (int step = 1; step < 128; step <<= 1) {
        __syncthreads();
        if ((tid & (2*step - 1)) == 0) {
            int o = tid*10, p = (tid + step)*10;
            int pa = 0, pb = 0;
            float ov[10]; int oi[10];
            #pragma unroll
            for (int j = 0; j < 10; j++) {
                float ka = sK[o + pa]; int ia = sI[o + pa];
                float kb = sK[p + pb]; int ib = sI[p + pb];
                if (better(ka, ia, kb, ib)) { ov[j] = ka; oi[j] = ia; pa++; }
                else                        { ov[j] = kb; oi[j] = ib; pb++; }
            }
            #pragma unroll
            for (int j = 0; j < 10; j++) { sK[o + j] = ov[j]; sI[o + j] = oi[j]; }
        }
    }
    __syncthreads();
}

__global__ void k_pass4() {
    int t = blockIdx.x, b = blockIdx.y, tid = threadIdx.x;
    int bt = b*TT + t;
    const float* irow = d_iou  + (size_t)bt * AA;
    const float* crow = d_cost + (size_t)bt * AA;
    __shared__ float sK[128*10];
    __shared__ int   sI[128*10];
    __shared__ int   s_dynk;
    float lk[10]; int li[10];

    // phase 0: top-10 iou -> dyn_k, rowmax
    #pragma unroll
    for (int j = 0; j < 10; j++) { lk[j] = -FLT_MAX; li[j] = INT_MAX; }
    for (int a = tid; a < AA; a += 128) top10_insert(lk, li, irow[a], a);
    #pragma unroll
    for (int j = 0; j < 10; j++) { sK[tid*10 + j] = lk[j]; sI[tid*10 + j] = li[j]; }
    merge_lists(sK, sI, tid);
    if (tid == 0) {
        float s = 0.f;
        #pragma unroll
        for (int j = 0; j < 10; j++) s += sK[j];
        int dk = (int)s;                 // truncation, matches astype(int32)
        if (dk < 1) dk = 1; if (dk > 10) dk = 10;
        s_dynk = dk;
        d_dynk[bt] = dk;
        d_rowmax[bt] = sK[0];
    }
    __syncthreads();

    // phase 1: top-10 of -cost -> selected anchors, scatter matches
    #pragma unroll
    for (int j = 0; j < 10; j++) { lk[j] = -FLT_MAX; li[j] = INT_MAX; }
    for (int a = tid; a < AA; a += 128) top10_insert(lk, li, -crow[a], a);
    #pragma unroll
    for (int j = 0; j < 10; j++) { sK[tid*10 + j] = lk[j]; sI[tid*10 + j] = li[j]; }
    merge_lists(sK, sI, tid);
    if (tid < 10) {
        int aa = sI[tid];
        if (tid < s_dynk && d_inb[b*AA + aa]) {
            atomicAdd(&d_mcnt[b*AA + aa], 1);
            atomicMin(&d_mt[b*AA + aa], t);
        }
    }
}

// ---------------- pass5: column ops + fused loss ----------------
__global__ void k_pass5(const float* __restrict__ pred, const float* __restrict__ target) {
    int b = blockIdx.y;
    int a = blockIdx.x * blockDim.x + threadIdx.x;
    int tid = threadIdx.x;
    __shared__ float s_rm[TT];
    if (tid < TT) s_rm[tid] = d_rowmax[b*TT + tid];
    __syncthreads();

    float t_lbox = 0.f, t_m = 0.f, t_lobj = 0.f, t_lcls = 0.f;
    if (a < AA) {
        int ba = b*AA + a;
        size_t base = (size_t)b*TT*AA + a;
        float piou = 0.f;
        float bestc = FLT_MAX; int bestt = 0;
        for (int t = 0; t < TT; t++) {
            float iv = d_iou[base + (size_t)t*AA];
            piou = fmaxf(piou, iv / (s_rm[t] + 1e-8f));
            float cv = d_cost[base + (size_t)t*AA];
            if (cv < bestc) { bestc = cv; bestt = t; }   // first min, matches argmin
        }
        bool inb = d_inb[ba] != 0;
        float objt = inb ? fminf(fmaxf(piou, 0.f), 1.f) : 0.f;
        const float* prow = pred + (size_t)ba * 85;
        t_lobj = bce(prow[4], objt);

        int cnt = d_mcnt[ba];
        int tp = -1;
        if (cnt == 1) tp = d_mt[ba];
        else if (cnt > 1) tp = bestt;
        if (tp >= 0) {
            t_m = 1.f;
            const float* tr = target + ((size_t)b*TT + tp) * 6;
            float tx1 = tr[2], ty1 = tr[3], tx2 = tr[4], ty2 = tr[5];
            int ci = (int)tr[1];
            float4 pb = d_pbox[ba];
            // CIoU
            float ltx = fmaxf(pb.x, tx1), lty = fmaxf(pb.y, ty1);
            float rbx = fminf(pb.z, tx2), rby = fminf(pb.w, ty2);
            float wx = fmaxf(rbx - ltx, 0.f), wy = fmaxf(rby - lty, 0.f);
            float inter = wx * wy;
            float wp = pb.z - pb.x, hp = pb.w - pb.y;
            float wt = tx2 - tx1, ht = ty2 - ty1;
            float iou = inter / (wp*hp + wt*ht - inter + 1e-8f);
            float cw = fmaxf(pb.z, tx2) - fminf(pb.x, tx1);
            float ch = fmaxf(pb.w, ty2) - fminf(pb.y, ty1);
            float c2 = cw*cw + ch*ch + 1e-8f;
            float dx = pb.x + pb.z - (tx1 + tx2);
            float dy = pb.y + pb.w - (ty1 + ty2);
            float rho2 = (dx*dx + dy*dy) * 0.25f;
            const float k4pi2 = (float)(4.0 / (M_PI * M_PI));
            float dv = atanf(wt / (ht + 1e-8f)) - atanf(wp / (hp + 1e-8f));
            float v = k4pi2 * dv * dv;
            float alpha = v / (1.f - iou + v + 1e-8f);
            float ciou = iou - rho2 / c2 - alpha * v;
            t_lbox = 1.f - ciou;
            float s = 0.f;
            for (int c = 0; c < CC; c++)
                s += bce(prow[5 + c], (c == ci) ? 1.f : 0.f);
            t_lcls = s * (1.0f / CC);
        }
    }

    // block reduction of 4 partials
    __shared__ float red[4*256];
    red[tid] = t_lbox; red[256 + tid] = t_m;
    red[512 + tid] = t_lobj; red[768 + tid] = t_lcls;
    __syncthreads();
    for (int s = 128; s > 0; s >>= 1) {
        if (tid < s) {
            red[tid]       += red[tid + s];
            red[256 + tid] += red[256 + tid + s];
            red[512 + tid] += red[512 + tid + s];
            red[768 + tid] += red[768 + tid + s];
        }
        __syncthreads();
    }
    if (tid == 0) {
        atomicAdd(&d_acc[0], (double)red[0]);
        atomicAdd(&d_acc[1], (double)red[256]);
        atomicAdd(&d_acc[2], (double)red[512]);
        atomicAdd(&d_acc[3], (double)red[768]);
    }
}

// ---------------- finalize ----------------
__global__ void k_final(float* out, int n) {
    double nm = d_acc[1];
    if (nm < 1.0) nm = 1.0;
    float lbox = (float)(0.05 * d_acc[0] / nm);
    float lobj = (float)(d_acc[2] / (double)(BB*AA));
    float lcls = (float)(0.5 * d_acc[3] / nm);
    float loss = lbox + lobj + lcls;
    if (n > 0) out[0] = loss;
    if (n > 1) out[1] = lbox;
    if (n > 2) out[2] = lobj;
    if (n > 3) out[3] = lcls;
}

// ---------------- launch ----------------
extern "C" void kernel_launch(void* const* d_in, const int* in_sizes, int n_in,
                              void* d_out, int out_size) {
    const float *pred = nullptr, *target = nullptr, *grid = nullptr, *stridem = nullptr;
    for (int i = 0; i < n_in; i++) {
        switch (in_sizes[i]) {
            case BB*AA*85:  pred    = (const float*)d_in[i]; break;
            case BB*TT*6:   target  = (const float*)d_in[i]; break;
            case AA*2:      grid    = (const float*)d_in[i]; break;
            case AA:        stridem = (const float*)d_in[i]; break;
            default: break;
        }
    }
    // positional fallback
    if (!pred    && n_in > 0) pred    = (const float*)d_in[0];
    if (!target  && n_in > 1) target  = (const float*)d_in[1];
    if (!grid    && n_in > 2) grid    = (const float*)d_in[2];
    if (!stridem && n_in > 3) stridem = (const float*)d_in[3];
    float* out = (float*)d_out;

    k_init<<<(BB*AA + 255)/256, 256>>>();
    k_anchor<<<(AA + 255)/256, 256>>>(grid, stridem);
    k_pass1<<<(BB*AA + 127)/128, 128>>>(pred);
    {
        dim3 g((AA + 255)/256, BB);
        k_pass2<<<g, 256>>>(target);
    }
    {
        dim3 g((AA + 255)/256, TT, BB);
        k_pass3<<<g, 256>>>(target);
    }
    {
        dim3 g(TT, BB);
        k_pass4<<<g, 128>>>();
    }
    {
        dim3 g((AA + 255)/256, BB);
        k_pass5<<<g, 256>>>(pred, target);
    }
    k_final<<<1, 1>>>(out, out_size);
}

// round 3
// speedup vs baseline: 1.7629x; 1.7343x over previous
#include <cuda_runtime.h>
#include <math.h>
#include <float.h>
#include <limits.h>
#include <stdint.h>

#define BB 16
#define AA 8400
#define TT 128
#define CC 80

// ---------------- scratch (static device globals; no allocation) ----------------
__device__ float d_S[BB*AA];                    // sum_c log1mp per anchor
__device__ float d_D[(size_t)BB*CC*AA];         // (logp - log1mp), class-major
__device__ float4 d_pbox[BB*AA];                // pred boxes packed
__device__ float4 d_anchor[AA];                 // xc, yc, stride
__device__ unsigned char d_inb[BB*AA];          // in_box (any target)
__device__ unsigned char d_any4[(size_t)4*BB*AA]; // per-chunk any flag
__device__ unsigned int d_ibc[BB*4*AA];         // in_box&in_center bitmask, word-major
__device__ float d_rowmax[BB*TT];
__device__ int   d_mcnt[BB*AA];
__device__ int   d_mt[BB*AA];
__device__ double d_acc[4];                     // lbox_sum, m_sum, lobj_sum, lcls_sum

__device__ __forceinline__ float bce(float x, float t) {
    return fmaxf(x, 0.f) - x * t + __logf(1.f + __expf(-fabsf(x)));
}
// jax.lax.top_k: stable — larger value first, ties -> smaller index first
__device__ __forceinline__ bool better(float k1, int i1, float k2, int i2) {
    return (k1 > k2) || (k1 == k2 && i1 < i2);
}

// register-resident top-10 insert: fully static indexing (no local-mem spill)
__device__ __forceinline__ void insert10(float (&lk)[10], int (&li)[10], float k, int i) {
    if (!better(k, i, lk[9], li[9])) return;
    bool p[10];
    #pragma unroll
    for (int q = 0; q < 10; q++) p[q] = better(k, i, lk[q], li[q]);
    #pragma unroll
    for (int q = 9; q >= 1; q--) {
        if (p[q]) {
            lk[q] = p[q-1] ? lk[q-1] : k;
            li[q] = p[q-1] ? li[q-1] : i;
        }
    }
    if (p[0]) { lk[0] = k; li[0] = i; }
}

// shared pair iou/cost computation — used identically by row and col kernels
__device__ __forceinline__ void pair_iou_cost(
    float4 pb, bool inb, bool ibc, float S, float Dv,
    float x1, float y1, float x2, float y2, float area_t,
    float& iou_out, float& cost_out)
{
    float ltx = fmaxf(x1, pb.x), lty = fmaxf(y1, pb.y);
    float rbx = fminf(x2, pb.z), rby = fminf(y2, pb.w);
    float wx = fmaxf(rbx - ltx, 0.f), wy = fmaxf(rby - lty, 0.f);
    float inter = wx * wy;
    float area_p = fmaxf(pb.z - pb.x, 0.f) * fmaxf(pb.w - pb.y, 0.f);
    float iou = inter / (area_t + area_p - inter + 1e-8f);
    iou = inb ? iou : 0.f;
    float iouc = -__logf(iou + 1e-8f);
    float clsc = -(S + Dv);
    float cost = fmaf(3.0f, iouc, clsc);
    if (!ibc) cost += 100000.0f;
    if (!inb) cost += 1000000000.0f;
    iou_out = iou;
    cost_out = cost;
}

// ---------------- init ----------------
__global__ void k_init() {
    int i = blockIdx.x * blockDim.x + threadIdx.x;
    if (i < BB*AA) { d_mcnt[i] = 0; d_mt[i] = INT_MAX; }
    if (i < 4) d_acc[i] = 0.0;
}

__global__ void k_anchor(const float* __restrict__ grid, const float* __restrict__ str) {
    int a = blockIdx.x * blockDim.x + threadIdx.x;
    if (a >= AA) return;
    float s = str[a];
    float4 v;
    v.x = (grid[2*a] + 0.5f) * s;
    v.y = (grid[2*a+1] + 0.5f) * s;
    v.z = s; v.w = 0.f;
    d_anchor[a] = v;
}

// ---------------- pass1: per-anchor class prob terms ----------------
__global__ void k_pass1(const float* __restrict__ pred) {
    int i = blockIdx.x * blockDim.x + threadIdx.x;
    if (i >= BB*AA) return;
    int b = i / AA, a = i - b*AA;
    const float* row = pred + (size_t)i * 85;
    float4 pb; pb.x = row[0]; pb.y = row[1]; pb.z = row[2]; pb.w = row[3];
    d_pbox[i] = pb;
    float so = 1.f / (1.f + __expf(-row[4]));
    float S = 0.f;
    #pragma unroll 4
    for (int c = 0; c < CC; c++) {
        float sc = 1.f / (1.f + __expf(-row[5 + c]));
        float p  = sqrtf(so * sc);
        float lp = fmaxf(__logf(p), -100.f);
        float l1 = fmaxf(__logf(1.f - p), -100.f);
        S += l1;
        d_D[((size_t)(b*CC + c)) * AA + a] = lp - l1;
    }
    d_S[i] = S;
}

// ---------------- pass2: geometric flags (4-way target-chunk split) ----------------
__global__ void k_flags(const float* __restrict__ target) {
    int b = blockIdx.z, ch = blockIdx.y;
    int a = blockIdx.x * blockDim.x + threadIdx.x;
    __shared__ float st[32*6];
    for (int i = threadIdx.x; i < 32*6; i += blockDim.x)
        st[i] = target[((size_t)b*TT + ch*32)*6 + i];
    __syncthreads();
    if (a >= AA) return;
    float4 an = d_anchor[a];
    float xc = an.x, yc = an.y, r = 2.5f * an.z;
    unsigned w = 0;
    bool any = false;
    #pragma unroll 4
    for (int tt = 0; tt < 32; tt++) {
        const float* tb = st + tt*6;
        float x1 = tb[2], y1 = tb[3], x2 = tb[4], y2 = tb[5];
        float dmin = fminf(fminf(xc - x1, yc - y1), fminf(x2 - xc, y2 - yc));
        bool ib = dmin > 0.f;
        float txc = (x1 + x2) * 0.5f, tyc = (y1 + y2) * 0.5f;
        bool ic = fmaxf(fabsf(xc - txc), fabsf(yc - tyc)) < r;
        any |= (ib || ic);
        if (ib && ic) w |= (1u << tt);
    }
    d_ibc[(b*4 + ch)*AA + a] = w;
    d_any4[((size_t)ch*BB + b)*AA + a] = any ? 1 : 0;
}

__global__ void k_combine() {
    int i = blockIdx.x * blockDim.x + threadIdx.x;
    if (i >= BB*AA) return;
    unsigned char v = d_any4[i] | d_any4[i + (size_t)BB*AA]
                    | d_any4[i + (size_t)2*BB*AA] | d_any4[i + (size_t)3*BB*AA];
    d_inb[i] = v;
}

// ---------------- row pass: fused iou/cost + dual top-10 + scatter ----------------
#define RW 256
__device__ __forceinline__ void merge_lists(volatile float* sK, volatile int* sI, int tid) {
    for (int step = 1; step < RW; step <<= 1) {
        __syncthreads();
        if ((tid & (2*step - 1)) == 0) {
            int o = tid*10, p = (tid + step)*10;
            int pa = 0, pb = 0;
            float ov[10]; int oi[10];
            #pragma unroll
            for (int j = 0; j < 10; j++) {
                float ka = sK[o + pa]; int ia = sI[o + pa];
                float kb = sK[p + pb]; int ib = sI[p + pb];
                if (better(ka, ia, kb, ib)) { ov[j] = ka; oi[j] = ia; pa++; }
                else                        { ov[j] = kb; oi[j] = ib; pb++; }
            }
            #pragma unroll
            for (int j = 0; j < 10; j++) { sK[o + j] = ov[j]; sI[o + j] = oi[j]; }
        }
    }
    __syncthreads();
}

__global__ __launch_bounds__(RW) void k_row(const float* __restrict__ target) {
    int t = blockIdx.x, b = blockIdx.y, tid = threadIdx.x;
    int bt = b*TT + t;
    const float* tr = target + (size_t)bt * 6;
    float x1 = tr[2], y1 = tr[3], x2 = tr[4], y2 = tr[5];
    int ci = (int)tr[1];
    float area_t = fmaxf(x2 - x1, 0.f) * fmaxf(y2 - y1, 0.f);

    const float* Srow = d_S + b*AA;
    const float* Drow = d_D + ((size_t)(b*CC + ci)) * AA;
    const float4* Prow = d_pbox + b*AA;
    const unsigned char* inbrow = d_inb + b*AA;
    const unsigned* wrow = d_ibc + (b*4 + (t >> 5))*AA;
    unsigned tbit = 1u << (t & 31);

    float lkI[10], lkC[10]; int liI[10], liC[10];
    #pragma unroll
    for (int j = 0; j < 10; j++) {
        lkI[j] = -FLT_MAX; liI[j] = INT_MAX;
        lkC[j] = -FLT_MAX; liC[j] = INT_MAX;
    }

    for (int a = tid; a < AA; a += RW) {
        float4 pb = Prow[a];
        bool inb = inbrow[a] != 0;
        bool ibc = (wrow[a] & tbit) != 0;
        float iou, cost;
        pair_iou_cost(pb, inb, ibc, Srow[a], Drow[a], x1, y1, x2, y2, area_t, iou, cost);
        insert10(lkI, liI, iou, a);
        insert10(lkC, liC, -cost, a);
    }

    __shared__ float sK[RW*10];
    __shared__ int   sI[RW*10];
    __shared__ int   s_dynk;

    // phase 0: merge iou lists -> dyn_k, rowmax
    #pragma unroll
    for (int j = 0; j < 10; j++) { sK[tid*10 + j] = lkI[j]; sI[tid*10 + j] = liI[j]; }
    merge_lists(sK, sI, tid);
    if (tid == 0) {
        float s = 0.f;
        #pragma unroll
        for (int j = 0; j < 10; j++) s += sK[j];
        int dk = (int)s;                 // truncation, matches astype(int32)
        if (dk < 1) dk = 1; if (dk > 10) dk = 10;
        s_dynk = dk;
        d_rowmax[bt] = sK[0];
    }
    __syncthreads();

    // phase 1: merge -cost lists -> scatter matches
    #pragma unroll
    for (int j = 0; j < 10; j++) { sK[tid*10 + j] = lkC[j]; sI[tid*10 + j] = liC[j]; }
    merge_lists(sK, sI, tid);
    if (tid < 10) {
        int aa = sI[tid];
        if (tid < s_dynk && inbrow[aa]) {
            atomicAdd(&d_mcnt[b*AA + aa], 1);
            atomicMin(&d_mt[b*AA + aa], t);
        }
    }
}

// ---------------- col pass: recompute + piou/argmin + fused loss ----------------
__global__ __launch_bounds__(256) void k_col(const float* __restrict__ pred,
                                             const float* __restrict__ target) {
    int b = blockIdx.y;
    int a = blockIdx.x * blockDim.x + threadIdx.x;
    int tid = threadIdx.x;
    __shared__ float s_t[TT*6];
    __shared__ float s_rm[TT];
    for (int i = tid; i < TT*6; i += blockDim.x)
        s_t[i] = target[(size_t)b*TT*6 + i];
    if (tid < TT) s_rm[tid] = d_rowmax[b*TT + tid];
    __syncthreads();

    float t_lbox = 0.f, t_m = 0.f, t_lobj = 0.f, t_lcls = 0.f;
    if (a < AA) {
        int ba = b*AA + a;
        float4 pb = d_pbox[ba];
        bool inb = d_inb[ba] != 0;
        float S = d_S[ba];

        float piou = 0.f;
        float bestc = FLT_MAX; int bestt = 0;
        for (int ch = 0; ch < 4; ch++) {
            unsigned w = d_ibc[(b*4 + ch)*AA + a];
            for (int tt = 0; tt < 32; tt++) {
                int t = ch*32 + tt;
                const float* tb = s_t + t*6;
                float x1 = tb[2], y1 = tb[3], x2 = tb[4], y2 = tb[5];
                int ci = (int)tb[1];
                float area_t = fmaxf(x2 - x1, 0.f) * fmaxf(y2 - y1, 0.f);
                bool ibc = (w >> tt) & 1u;
                float iou, cost;
                pair_iou_cost(pb, inb, ibc, S, d_D[((size_t)(b*CC + ci))*AA + a],
                              x1, y1, x2, y2, area_t, iou, cost);
                piou = fmaxf(piou, iou / (s_rm[t] + 1e-8f));
                if (cost < bestc) { bestc = cost; bestt = t; }   // first min = argmin
            }
        }

        float objt = inb ? fminf(fmaxf(piou, 0.f), 1.f) : 0.f;
        const float* prow = pred + (size_t)ba * 85;
        t_lobj = bce(prow[4], objt);

        int cnt = d_mcnt[ba];
        int tp = -1;
        if (cnt == 1) tp = d_mt[ba];
        else if (cnt > 1) tp = bestt;
        if (tp >= 0) {
            t_m = 1.f;
            const float* tb = s_t + tp*6;
            float tx1 = tb[2], ty1 = tb[3], tx2 = tb[4], ty2 = tb[5];
            int ci = (int)tb[1];
            // CIoU
            float ltx = fmaxf(pb.x, tx1), lty = fmaxf(pb.y, ty1);
            float rbx = fminf(pb.z, tx2), rby = fminf(pb.w, ty2);
            float wx = fmaxf(rbx - ltx, 0.f), wy = fmaxf(rby - lty, 0.f);
            float inter = wx * wy;
            float wp = pb.z - pb.x, hp = pb.w - pb.y;
            float wt = tx2 - tx1, ht = ty2 - ty1;
            float iou = inter / (wp*hp + wt*ht - inter + 1e-8f);
            float cw = fmaxf(pb.z, tx2) - fminf(pb.x, tx1);
            float chh = fmaxf(pb.w, ty2) - fminf(pb.y, ty1);
            float c2 = cw*cw + chh*chh + 1e-8f;
            float dx = pb.x + pb.z - (tx1 + tx2);
            float dy = pb.y + pb.w - (ty1 + ty2);
            float rho2 = (dx*dx + dy*dy) * 0.25f;
            const float k4pi2 = (float)(4.0 / (M_PI * M_PI));
            float dv = atanf(wt / (ht + 1e-8f)) - atanf(wp / (hp + 1e-8f));
            float v = k4pi2 * dv * dv;
            float alpha = v / (1.f - iou + v + 1e-8f);
            float ciou = iou - rho2 / c2 - alpha * v;
            t_lbox = 1.f - ciou;
            float s = 0.f;
            for (int c = 0; c < CC; c++)
                s += bce(prow[5 + c], (c == ci) ? 1.f : 0.f);
            t_lcls = s * (1.0f / CC);
        }
    }

    // block reduction of 4 partials
    __shared__ float red[4*256];
    red[tid] = t_lbox; red[256 + tid] = t_m;
    red[512 + tid] = t_lobj; red[768 + tid] = t_lcls;
    __syncthreads();
    for (int s = 128; s > 0; s >>= 1) {
        if (tid < s) {
            red[tid]       += red[tid + s];
            red[256 + tid] += red[256 + tid + s];
            red[512 + tid] += red[512 + tid + s];
            red[768 + tid] += red[768 + tid + s];
        }
        __syncthreads();
    }
    if (tid == 0) {
        atomicAdd(&d_acc[0], (double)red[0]);
        atomicAdd(&d_acc[1], (double)red[256]);
        atomicAdd(&d_acc[2], (double)red[512]);
        atomicAdd(&d_acc[3], (double)red[768]);
    }
}

// ---------------- finalize ----------------
__global__ void k_final(float* out, int n) {
    double nm = d_acc[1];
    if (nm < 1.0) nm = 1.0;
    float lbox = (float)(0.05 * d_acc[0] / nm);
    float lobj = (float)(d_acc[2] / (double)(BB*AA));
    float lcls = (float)(0.5 * d_acc[3] / nm);
    float loss = lbox + lobj + lcls;
    if (n > 0) out[0] = loss;
    if (n > 1) out[1] = lbox;
    if (n > 2) out[2] = lobj;
    if (n > 3) out[3] = lcls;
}

// ---------------- launch ----------------
extern "C" void kernel_launch(void* const* d_in, const int* in_sizes, int n_in,
                              void* d_out, int out_size) {
    const float *pred = nullptr, *target = nullptr, *grid = nullptr, *stridem = nullptr;
    for (int i = 0; i < n_in; i++) {
        switch (in_sizes[i]) {
            case BB*AA*85:  pred    = (const float*)d_in[i]; break;
            case BB*TT*6:   target  = (const float*)d_in[i]; break;
            case AA*2:      grid    = (const float*)d_in[i]; break;
            case AA:        stridem = (const float*)d_in[i]; break;
            default: break;
        }
    }
    if (!pred    && n_in > 0) pred    = (const float*)d_in[0];
    if (!target  && n_in > 1) target  = (const float*)d_in[1];
    if (!grid    && n_in > 2) grid    = (const float*)d_in[2];
    if (!stridem && n_in > 3) stridem = (const float*)d_in[3];
    float* out = (float*)d_out;

    k_init<<<(BB*AA + 255)/256, 256>>>();
    k_anchor<<<(AA + 255)/256, 256>>>(grid, stridem);
    k_pass1<<<(BB*AA + 127)/128, 128>>>(pred);
    {
        dim3 g((AA + 255)/256, 4, BB);
        k_flags<<<g, 256>>>(target);
    }
    k_combine<<<(BB*AA + 255)/256, 256>>>();
    {
        dim3 g(TT, BB);
        k_row<<<g, RW>>>(target);
    }
    {
        dim3 g((AA + 255)/256, BB);
        k_col<<<g, 256>>>(pred, target);
    }
    k_final<<<1, 1>>>(out, out_size);
}

// round 4
// speedup vs baseline: 2.1318x; 1.2092x over previous
#include <cuda_runtime.h>
#include <math.h>
#include <float.h>
#include <limits.h>
#include <stdint.h>

#define BB 16
#define AA 8400
#define TT 128
#define CC 80
#define NN (BB*AA)

// ---------------- scratch (static device globals; no allocation) ----------------
__device__ float d_predT[(size_t)85*NN];        // transposed pred [channel][b*A]
__device__ float d_D[(size_t)BB*CC*AA];         // (logp - log1mp), class-major
__device__ float2 d_SI[NN];                     // {S, in_box}
__device__ float4 d_pbox[NN];                   // pred boxes packed
__device__ float4 d_anchor[AA];                 // xc, yc, stride
__device__ unsigned char d_inb[NN];             // in_box byte
__device__ unsigned char d_any4[(size_t)4*NN];  // per-chunk any flag
__device__ unsigned int d_ibc[BB*4*AA];         // in_box&in_center bitmask, word-major
__device__ float d_rowmax[BB*TT];
__device__ int   d_mcnt[NN];
__device__ int   d_mt[NN];
__device__ double d_acc[4];                     // lbox_sum, m_sum, lobj_sum, lcls_sum

__device__ __forceinline__ float bce(float x, float t) {
    return fmaxf(x, 0.f) - x * t + __logf(1.f + __expf(-fabsf(x)));
}
// jax.lax.top_k: stable — larger value first, ties -> smaller index first
__device__ __forceinline__ bool better(float k1, int i1, float k2, int i2) {
    return (k1 > k2) || (k1 == k2 && i1 < i2);
}

// register-resident top-10 insert: fully static indexing (no local-mem spill)
__device__ __forceinline__ void insert10(float (&lk)[10], int (&li)[10], float k, int i) {
    if (!better(k, i, lk[9], li[9])) return;
    bool p[10];
    #pragma unroll
    for (int q = 0; q < 10; q++) p[q] = better(k, i, lk[q], li[q]);
    #pragma unroll
    for (int q = 9; q >= 1; q--) {
        if (p[q]) {
            lk[q] = p[q-1] ? lk[q-1] : k;
            li[q] = p[q-1] ? li[q-1] : i;
        }
    }
    if (p[0]) { lk[0] = k; li[0] = i; }
}

// shared pair iou/cost computation — used identically by row and col kernels
__device__ __forceinline__ void pair_iou_cost(
    float4 pb, bool inb, bool ibc, float S, float Dv,
    float x1, float y1, float x2, float y2, float area_t,
    float& iou_out, float& cost_out)
{
    float ltx = fmaxf(x1, pb.x), lty = fmaxf(y1, pb.y);
    float rbx = fminf(x2, pb.z), rby = fminf(y2, pb.w);
    float wx = fmaxf(rbx - ltx, 0.f), wy = fmaxf(rby - lty, 0.f);
    float inter = wx * wy;
    float area_p = fmaxf(pb.z - pb.x, 0.f) * fmaxf(pb.w - pb.y, 0.f);
    float iou = __fdividef(inter, area_t + area_p - inter + 1e-8f);
    iou = inb ? iou : 0.f;
    float iouc = -__logf(iou + 1e-8f);
    float clsc = -(S + Dv);
    float cost = fmaf(3.0f, iouc, clsc);
    if (!ibc) cost += 100000.0f;
    if (!inb) cost += 1000000000.0f;
    iou_out = iou;
    cost_out = cost;
}

// ---------------- init ----------------
__global__ void k_init() {
    int i = blockIdx.x * blockDim.x + threadIdx.x;
    if (i < NN) { d_mcnt[i] = 0; d_mt[i] = INT_MAX; }
    if (i < 4) d_acc[i] = 0.0;
}

__global__ void k_anchor(const float* __restrict__ grid, const float* __restrict__ str) {
    int a = blockIdx.x * blockDim.x + threadIdx.x;
    if (a >= AA) return;
    float s = str[a];
    float4 v;
    v.x = (grid[2*a] + 0.5f) * s;
    v.y = (grid[2*a+1] + 0.5f) * s;
    v.z = s; v.w = 0.f;
    d_anchor[a] = v;
}

// ---------------- transpose pred [N][85] -> [85][N] ----------------
__global__ __launch_bounds__(256) void k_transpose(const float* __restrict__ in) {
    __shared__ float tile[32][33];
    int x = blockIdx.x * 32 + threadIdx.x;         // channel (0..84)
    int y0 = blockIdx.y * 32;                      // anchor base
    #pragma unroll
    for (int j = 0; j < 32; j += 8) {
        int y = y0 + threadIdx.y + j;
        if (x < 85 && y < NN)
            tile[threadIdx.y + j][threadIdx.x] = in[(size_t)y * 85 + x];
    }
    __syncthreads();
    int xo = y0 + threadIdx.x;                     // anchor
    int yo = blockIdx.x * 32 + threadIdx.y;        // channel
    #pragma unroll
    for (int j = 0; j < 32; j += 8) {
        int c = yo + j;
        if (xo < NN && c < 85)
            d_predT[(size_t)c * NN + xo] = tile[threadIdx.x][threadIdx.y + j];
    }
}

// ---------------- pass1: per-anchor class prob terms (coalesced, no div) ----------------
__global__ __launch_bounds__(256) void k_pass1() {
    int i = blockIdx.x * blockDim.x + threadIdx.x;
    if (i >= NN) return;
    int b = i / AA, a = i - b*AA;
    float4 pb;
    pb.x = d_predT[(size_t)0*NN + i];
    pb.y = d_predT[(size_t)1*NN + i];
    pb.z = d_predT[(size_t)2*NN + i];
    pb.w = d_predT[(size_t)3*NN + i];
    d_pbox[i] = pb;
    float xo = d_predT[(size_t)4*NN + i];
    float A0 = 1.f + __expf(-xo);
    float S = 0.f;
    size_t dbase = (size_t)b*CC*AA + a;
    #pragma unroll 4
    for (int c = 0; c < CC; c++) {
        float xc = d_predT[(size_t)(5 + c)*NN + i];
        float u  = A0 * (1.f + __expf(-xc));     // = 1/(so*sc)
        float p  = rsqrtf(u);
        float lp = fmaxf(-0.5f * __logf(u), -100.f);
        float l1 = fmaxf(__logf(1.f - p), -100.f);
        S += l1;
        d_D[dbase + (size_t)c*AA] = lp - l1;
    }
    d_SI[i].x = S;
}

// ---------------- flags: geometric (4-way target-chunk split) ----------------
__global__ void k_flags(const float* __restrict__ target) {
    int b = blockIdx.z, ch = blockIdx.y;
    int a = blockIdx.x * blockDim.x + threadIdx.x;
    __shared__ float st[32*6];
    for (int i = threadIdx.x; i < 32*6; i += blockDim.x)
        st[i] = target[((size_t)b*TT + ch*32)*6 + i];
    __syncthreads();
    if (a >= AA) return;
    float4 an = d_anchor[a];
    float xc = an.x, yc = an.y, r = 2.5f * an.z;
    unsigned w = 0;
    bool any = false;
    #pragma unroll 4
    for (int tt = 0; tt < 32; tt++) {
        const float* tb = st + tt*6;
        float x1 = tb[2], y1 = tb[3], x2 = tb[4], y2 = tb[5];
        float dmin = fminf(fminf(xc - x1, yc - y1), fminf(x2 - xc, y2 - yc));
        bool ib = dmin > 0.f;
        float txc = (x1 + x2) * 0.5f, tyc = (y1 + y2) * 0.5f;
        bool ic = fmaxf(fabsf(xc - txc), fabsf(yc - tyc)) < r;
        any |= (ib || ic);
        if (ib && ic) w |= (1u << tt);
    }
    d_ibc[(b*4 + ch)*AA + a] = w;
    d_any4[((size_t)ch*NN) + b*AA + a] = any ? 1 : 0;
}

__global__ void k_combine() {
    int i = blockIdx.x * blockDim.x + threadIdx.x;
    if (i >= NN) return;
    unsigned char v = d_any4[i] | d_any4[i + (size_t)NN]
                    | d_any4[i + (size_t)2*NN] | d_any4[i + (size_t)3*NN];
    d_inb[i] = v;
    d_SI[i].y = v ? 1.f : 0.f;
}

// ---------------- row pass: warp-per-row, dual top-10, scatter ----------------
__device__ __forceinline__ void warp_merge10(float* K, int* I, int lane) {
    for (int step = 1; step < 32; step <<= 1) {
        __syncwarp();
        if ((lane & (2*step - 1)) == 0) {
            int o = lane*10, p = (lane + step)*10;
            int pa = 0, pb = 0;
            float ov[10]; int oi[10];
            #pragma unroll
            for (int j = 0; j < 10; j++) {
                float ka = K[o + pa]; int ia = I[o + pa];
                float kb = K[p + pb]; int ib = I[p + pb];
                if (better(ka, ia, kb, ib)) { ov[j] = ka; oi[j] = ia; pa++; }
                else                        { ov[j] = kb; oi[j] = ib; pb++; }
            }
            #pragma unroll
            for (int j = 0; j < 10; j++) { K[o + j] = ov[j]; I[o + j] = oi[j]; }
        }
    }
    __syncwarp();
}

#define ROWS_PER_BLK 4
__global__ __launch_bounds__(128) void k_row(const float* __restrict__ target) {
    int warp = threadIdx.x >> 5, lane = threadIdx.x & 31;
    int row = blockIdx.x * ROWS_PER_BLK + warp;    // = b*TT + t
    int b = row >> 7, t = row & (TT-1);
    const float* tr = target + (size_t)row * 6;
    float x1 = tr[2], y1 = tr[3], x2 = tr[4], y2 = tr[5];
    int ci = (int)tr[1];
    float area_t = fmaxf(x2 - x1, 0.f) * fmaxf(y2 - y1, 0.f);

    const float2* SIrow = d_SI + b*AA;
    const float* Drow = d_D + ((size_t)(b*CC + ci)) * AA;
    const float4* Prow = d_pbox + b*AA;
    const unsigned* wrow = d_ibc + (b*4 + (t >> 5))*AA;
    unsigned tbit = 1u << (t & 31);

    float lkI[10], lkC[10]; int liI[10], liC[10];
    #pragma unroll
    for (int j = 0; j < 10; j++) {
        lkI[j] = -FLT_MAX; liI[j] = INT_MAX;
        lkC[j] = -FLT_MAX; liC[j] = INT_MAX;
    }

    for (int a = lane; a < AA; a += 32) {
        float4 pb = Prow[a];
        float2 si = SIrow[a];
        bool inb = si.y != 0.f;
        bool ibc = (wrow[a] & tbit) != 0;
        float iou, cost;
        pair_iou_cost(pb, inb, ibc, si.x, Drow[a], x1, y1, x2, y2, area_t, iou, cost);
        insert10(lkI, liI, iou, a);
        insert10(lkC, liC, -cost, a);
    }

    __shared__ float sK[128*10];
    __shared__ int   sI[128*10];
    float* wK = sK + warp*320;
    int*   wI = sI + warp*320;

    // phase 0: iou -> dyn_k, rowmax
    #pragma unroll
    for (int j = 0; j < 10; j++) { wK[lane*10 + j] = lkI[j]; wI[lane*10 + j] = liI[j]; }
    warp_merge10(wK, wI, lane);
    int dk = 0;
    if (lane == 0) {
        float s = 0.f;
        #pragma unroll
        for (int j = 0; j < 10; j++) s += wK[j];
        dk = (int)s;                 // truncation, matches astype(int32)
        if (dk < 1) dk = 1; if (dk > 10) dk = 10;
        d_rowmax[row] = wK[0];
    }
    dk = __shfl_sync(0xffffffffu, dk, 0);
    __syncwarp();

    // phase 1: -cost -> scatter matches
    #pragma unroll
    for (int j = 0; j < 10; j++) { wK[lane*10 + j] = lkC[j]; wI[lane*10 + j] = liC[j]; }
    warp_merge10(wK, wI, lane);
    if (lane < 10 && lane < dk) {
        int aa = wI[lane];
        if (d_inb[b*AA + aa]) {
            atomicAdd(&d_mcnt[b*AA + aa], 1);
            atomicMin(&d_mt[b*AA + aa], t);
        }
    }
}

// ---------------- col pass: recompute + piou/argmin + fused loss ----------------
__global__ __launch_bounds__(256) void k_col(const float* __restrict__ target) {
    int b = blockIdx.y;
    int a = blockIdx.x * blockDim.x + threadIdx.x;
    int tid = threadIdx.x;
    __shared__ float s_x1[TT], s_y1[TT], s_x2[TT], s_y2[TT], s_ar[TT], s_inv[TT];
    __shared__ int   s_cia[TT];
    if (tid < TT) {
        const float* tb = target + ((size_t)b*TT + tid)*6;
        float X1 = tb[2], Y1 = tb[3], X2 = tb[4], Y2 = tb[5];
        s_x1[tid] = X1; s_y1[tid] = Y1; s_x2[tid] = X2; s_y2[tid] = Y2;
        s_ar[tid] = fmaxf(X2 - X1, 0.f) * fmaxf(Y2 - Y1, 0.f);
        s_cia[tid] = (b*CC + (int)tb[1]) * AA;
        s_inv[tid] = __fdividef(1.f, d_rowmax[b*TT + tid] + 1e-8f);
    }
    __syncthreads();

    float t_lbox = 0.f, t_m = 0.f, t_lobj = 0.f, t_lcls = 0.f;
    if (a < AA) {
        int ba = b*AA + a;
        float4 pb = d_pbox[ba];
        float2 si = d_SI[ba];
        bool inb = si.y != 0.f;
        float S = si.x;
        unsigned wv[4];
        #pragma unroll
        for (int ch = 0; ch < 4; ch++) wv[ch] = d_ibc[(b*4 + ch)*AA + a];

        float piou = 0.f;
        float bestc = FLT_MAX; int bestt = 0;
        #pragma unroll 4
        for (int t = 0; t < TT; t++) {
            bool ibc = (wv[t >> 5] >> (t & 31)) & 1u;
            float iou, cost;
            pair_iou_cost(pb, inb, ibc, S, d_D[(size_t)s_cia[t] + a],
                          s_x1[t], s_y1[t], s_x2[t], s_y2[t], s_ar[t], iou, cost);
            piou = fmaxf(piou, iou * s_inv[t]);
            if (cost < bestc) { bestc = cost; bestt = t; }   // first min = argmin
        }

        float objt = inb ? fminf(fmaxf(piou, 0.f), 1.f) : 0.f;
        t_lobj = bce(d_predT[(size_t)4*NN + ba], objt);

        int cnt = d_mcnt[ba];
        int tp = -1;
        if (cnt == 1) tp = d_mt[ba];
        else if (cnt > 1) tp = bestt;
        if (tp >= 0) {
            t_m = 1.f;
            float tx1 = s_x1[tp], ty1 = s_y1[tp], tx2 = s_x2[tp], ty2 = s_y2[tp];
            int ci = s_cia[tp] / AA - b*CC;
            // CIoU
            float ltx = fmaxf(pb.x, tx1), lty = fmaxf(pb.y, ty1);
            float rbx = fminf(pb.z, tx2), rby = fminf(pb.w, ty2);
            float wx = fmaxf(rbx - ltx, 0.f), wy = fmaxf(rby - lty, 0.f);
            float inter = wx * wy;
            float wp = pb.z - pb.x, hp = pb.w - pb.y;
            float wt = tx2 - tx1, ht = ty2 - ty1;
            float iou = inter / (wp*hp + wt*ht - inter + 1e-8f);
            float cw = fmaxf(pb.z, tx2) - fminf(pb.x, tx1);
            float chh = fmaxf(pb.w, ty2) - fminf(pb.y, ty1);
            float c2 = cw*cw + chh*chh + 1e-8f;
            float dx = pb.x + pb.z - (tx1 + tx2);
            float dy = pb.y + pb.w - (ty1 + ty2);
            float rho2 = (dx*dx + dy*dy) * 0.25f;
            const float k4pi2 = (float)(4.0 / (M_PI * M_PI));
            float dv = atanf(wt / (ht + 1e-8f)) - atanf(wp / (hp + 1e-8f));
            float v = k4pi2 * dv * dv;
            float alpha = v / (1.f - iou + v + 1e-8f);
            float ciou = iou - rho2 / c2 - alpha * v;
            t_lbox = 1.f - ciou;
            float s = 0.f;
            for (int c = 0; c < CC; c++)
                s += bce(d_predT[(size_t)(5 + c)*NN + ba], (c == ci) ? 1.f : 0.f);
            t_lcls = s * (1.0f / CC);
        }
    }

    // block reduction of 4 partials
    __shared__ float red[4*256];
    red[tid] = t_lbox; red[256 + tid] = t_m;
    red[512 + tid] = t_lobj; red[768 + tid] = t_lcls;
    __syncthreads();
    for (int s = 128; s > 0; s >>= 1) {
        if (tid < s) {
            red[tid]       += red[tid + s];
            red[256 + tid] += red[256 + tid + s];
            red[512 + tid] += red[512 + tid + s];
            red[768 + tid] += red[768 + tid + s];
        }
        __syncthreads();
    }
    if (tid == 0) {
        atomicAdd(&d_acc[0], (double)red[0]);
        atomicAdd(&d_acc[1], (double)red[256]);
        atomicAdd(&d_acc[2], (double)red[512]);
        atomicAdd(&d_acc[3], (double)red[768]);
    }
}

// ---------------- finalize ----------------
__global__ void k_final(float* out, int n) {
    double nm = d_acc[1];
    if (nm < 1.0) nm = 1.0;
    float lbox = (float)(0.05 * d_acc[0] / nm);
    float lobj = (float)(d_acc[2] / (double)(NN));
    float lcls = (float)(0.5 * d_acc[3] / nm);
    float loss = lbox + lobj + lcls;
    if (n > 0) out[0] = loss;
    if (n > 1) out[1] = lbox;
    if (n > 2) out[2] = lobj;
    if (n > 3) out[3] = lcls;
}

// ---------------- launch ----------------
extern "C" void kernel_launch(void* const* d_in, const int* in_sizes, int n_in,
                              void* d_out, int out_size) {
    const float *pred = nullptr, *target = nullptr, *grid = nullptr, *stridem = nullptr;
    for (int i = 0; i < n_in; i++) {
        switch (in_sizes[i]) {
            case BB*AA*85:  pred    = (const float*)d_in[i]; break;
            case BB*TT*6:   target  = (const float*)d_in[i]; break;
            case AA*2:      grid    = (const float*)d_in[i]; break;
            case AA:        stridem = (const float*)d_in[i]; break;
            default: break;
        }
    }
    if (!pred    && n_in > 0) pred    = (const float*)d_in[0];
    if (!target  && n_in > 1) target  = (const float*)d_in[1];
    if (!grid    && n_in > 2) grid    = (const float*)d_in[2];
    if (!stridem && n_in > 3) stridem = (const float*)d_in[3];
    float* out = (float*)d_out;

    k_init<<<(NN + 255)/256, 256>>>();
    k_anchor<<<(AA + 255)/256, 256>>>(grid, stridem);
    {
        dim3 g(3, (NN + 31)/32);
        dim3 blk(32, 8);
        k_transpose<<<g, blk>>>(pred);
    }
    k_pass1<<<(NN + 255)/256, 256>>>();
    {
        dim3 g((AA + 255)/256, 4, BB);
        k_flags<<<g, 256>>>(target);
    }
    k_combine<<<(NN + 255)/256, 256>>>();
    k_row<<<(BB*TT)/ROWS_PER_BLK, 128>>>(target);
    {
        dim3 g((AA + 255)/256, BB);
        k_col<<<g, 256>>>(target);
    }
    k_final<<<1, 1>>>(out, out_size);
}

// round 5
// speedup vs baseline: 2.1466x; 1.0069x over previous
#include <cuda_runtime.h>
#include <math.h>
#include <float.h>
#include <limits.h>
#include <stdint.h>

#define BB 16
#define AA 8400
#define TT 128
#define CC 80
#define NN (BB*AA)
#define NG 8          // class groups in pass1
#define CG (CC/NG)    // classes per group

// ---------------- scratch (static device globals; no allocation) ----------------
__device__ float d_predT[(size_t)85*NN];        // transposed pred [channel][b*A]
__device__ float d_D[(size_t)BB*CC*AA];         // (logp - log1mp), class-major
__device__ float d_Spart[(size_t)NG*NN];        // partial log1mp sums per group
__device__ float2 d_SI[NN];                     // {S, in_box}
__device__ float4 d_pbox[NN];                   // pred boxes packed
__device__ float4 d_anchor[AA];                 // xc, yc, stride
__device__ unsigned char d_inb[NN];             // in_box byte
__device__ unsigned char d_any4[(size_t)4*NN];  // per-chunk any flag
__device__ unsigned int d_ibc[BB*4*AA];         // in_box&in_center bitmask, word-major
__device__ float d_rowmax[BB*TT];
__device__ int   d_mcnt[NN];
__device__ int   d_mt[NN];
__device__ double d_acc[4];                     // lbox_sum, m_sum, lobj_sum, lcls_sum

__device__ __forceinline__ float bce(float x, float t) {
    return fmaxf(x, 0.f) - x * t + __logf(1.f + __expf(-fabsf(x)));
}
// jax.lax.top_k: stable — larger value first, ties -> smaller index first
__device__ __forceinline__ bool better(float k1, int i1, float k2, int i2) {
    return (k1 > k2) || (k1 == k2 && i1 < i2);
}

// register-resident top-10 insert: fully static indexing (no local-mem spill)
__device__ __forceinline__ void insert10(float (&lk)[10], int (&li)[10], float k, int i) {
    if (!better(k, i, lk[9], li[9])) return;
    bool p[10];
    #pragma unroll
    for (int q = 0; q < 10; q++) p[q] = better(k, i, lk[q], li[q]);
    #pragma unroll
    for (int q = 9; q >= 1; q--) {
        if (p[q]) {
            lk[q] = p[q-1] ? lk[q-1] : k;
            li[q] = p[q-1] ? li[q-1] : i;
        }
    }
    if (p[0]) { lk[0] = k; li[0] = i; }
}

// shared pair iou/cost computation — used identically by row and col kernels
__device__ __forceinline__ void pair_iou_cost(
    float4 pb, bool inb, bool ibc, float S, float Dv,
    float x1, float y1, float x2, float y2, float area_t,
    float& iou_out, float& cost_out)
{
    float ltx = fmaxf(x1, pb.x), lty = fmaxf(y1, pb.y);
    float rbx = fminf(x2, pb.z), rby = fminf(y2, pb.w);
    float wx = fmaxf(rbx - ltx, 0.f), wy = fmaxf(rby - lty, 0.f);
    float inter = wx * wy;
    float area_p = fmaxf(pb.z - pb.x, 0.f) * fmaxf(pb.w - pb.y, 0.f);
    float iou = __fdividef(inter, area_t + area_p - inter + 1e-8f);
    iou = inb ? iou : 0.f;
    float iouc = -__logf(iou + 1e-8f);
    float clsc = -(S + Dv);
    float cost = fmaf(3.0f, iouc, clsc);
    if (!ibc) cost += 100000.0f;
    if (!inb) cost += 1000000000.0f;
    iou_out = iou;
    cost_out = cost;
}

// ---------------- init (+anchor fused) ----------------
__global__ void k_init(const float* __restrict__ grid, const float* __restrict__ str) {
    int i = blockIdx.x * blockDim.x + threadIdx.x;
    if (i < NN) { d_mcnt[i] = 0; d_mt[i] = INT_MAX; }
    if (i < 4) d_acc[i] = 0.0;
    if (i < AA) {
        float s = str[i];
        float4 v;
        v.x = (grid[2*i] + 0.5f) * s;
        v.y = (grid[2*i+1] + 0.5f) * s;
        v.z = s; v.w = 0.f;
        d_anchor[i] = v;
    }
}

// ---------------- transpose pred [N][85] -> [85][N] ----------------
__global__ __launch_bounds__(256) void k_transpose(const float* __restrict__ in) {
    __shared__ float tile[32][33];
    int x = blockIdx.x * 32 + threadIdx.x;         // channel (0..84)
    int y0 = blockIdx.y * 32;                      // anchor base
    #pragma unroll
    for (int j = 0; j < 32; j += 8) {
        int y = y0 + threadIdx.y + j;
        if (x < 85 && y < NN)
            tile[threadIdx.y + j][threadIdx.x] = in[(size_t)y * 85 + x];
    }
    __syncthreads();
    int xo = y0 + threadIdx.x;                     // anchor
    int yo = blockIdx.x * 32 + threadIdx.y;        // channel
    #pragma unroll
    for (int j = 0; j < 32; j += 8) {
        int c = yo + j;
        if (xo < NN && c < 85)
            d_predT[(size_t)c * NN + xo] = tile[threadIdx.x][threadIdx.y + j];
    }
}

// ---------------- pass1: class prob terms, split over NG class groups ----------------
__global__ __launch_bounds__(256) void k_pass1() {
    int i = blockIdx.x * blockDim.x + threadIdx.x;
    int g = blockIdx.y;
    if (i >= NN) return;
    int b = i / AA, a = i - b*AA;
    if (g == 0) {
        float4 pb;
        pb.x = d_predT[(size_t)0*NN + i];
        pb.y = d_predT[(size_t)1*NN + i];
        pb.z = d_predT[(size_t)2*NN + i];
        pb.w = d_predT[(size_t)3*NN + i];
        d_pbox[i] = pb;
    }
    float xo = d_predT[(size_t)4*NN + i];
    float A0 = 1.f + __expf(-xo);
    float S = 0.f;
    size_t dbase = (size_t)b*CC*AA + a;
    int c0 = g * CG;
    #pragma unroll
    for (int cc = 0; cc < CG; cc++) {
        int c = c0 + cc;
        float xc = d_predT[(size_t)(5 + c)*NN + i];
        float u  = A0 * (1.f + __expf(-xc));     // = 1/(so*sc)
        float p  = rsqrtf(u);
        float lp = fmaxf(-0.5f * __logf(u), -100.f);
        float l1 = fmaxf(__logf(1.f - p), -100.f);
        S += l1;
        d_D[dbase + (size_t)c*AA] = lp - l1;
    }
    d_Spart[(size_t)g*NN + i] = S;
}

// ---------------- flags: geometric (4-way target-chunk split) ----------------
__global__ void k_flags(const float* __restrict__ target) {
    int b = blockIdx.z, ch = blockIdx.y;
    int a = blockIdx.x * blockDim.x + threadIdx.x;
    __shared__ float st[32*6];
    for (int i = threadIdx.x; i < 32*6; i += blockDim.x)
        st[i] = target[((size_t)b*TT + ch*32)*6 + i];
    __syncthreads();
    if (a >= AA) return;
    float4 an = d_anchor[a];
    float xc = an.x, yc = an.y, r = 2.5f * an.z;
    unsigned w = 0;
    bool any = false;
    #pragma unroll 4
    for (int tt = 0; tt < 32; tt++) {
        const float* tb = st + tt*6;
        float x1 = tb[2], y1 = tb[3], x2 = tb[4], y2 = tb[5];
        float dmin = fminf(fminf(xc - x1, yc - y1), fminf(x2 - xc, y2 - yc));
        bool ib = dmin > 0.f;
        float txc = (x1 + x2) * 0.5f, tyc = (y1 + y2) * 0.5f;
        bool ic = fmaxf(fabsf(xc - txc), fabsf(yc - tyc)) < r;
        any |= (ib || ic);
        if (ib && ic) w |= (1u << tt);
    }
    d_ibc[(b*4 + ch)*AA + a] = w;
    d_any4[((size_t)ch*NN) + b*AA + a] = any ? 1 : 0;
}

// combine: in_box OR + partial-S sum
__global__ void k_combine() {
    int i = blockIdx.x * blockDim.x + threadIdx.x;
    if (i >= NN) return;
    unsigned char v = d_any4[i] | d_any4[i + (size_t)NN]
                    | d_any4[i + (size_t)2*NN] | d_any4[i + (size_t)3*NN];
    d_inb[i] = v;
    float S = 0.f;
    #pragma unroll
    for (int g = 0; g < NG; g++) S += d_Spart[(size_t)g*NN + i];
    float2 si; si.x = S; si.y = v ? 1.f : 0.f;
    d_SI[i] = si;
}

// ---------------- row pass: 2 warps per row, dual top-10, scatter ----------------
__device__ __forceinline__ void warp_merge10(float* K, int* I, int lane) {
    for (int step = 1; step < 32; step <<= 1) {
        __syncwarp();
        if ((lane & (2*step - 1)) == 0) {
            int o = lane*10, p = (lane + step)*10;
            int pa = 0, pb = 0;
            float ov[10]; int oi[10];
            #pragma unroll
            for (int j = 0; j < 10; j++) {
                float ka = K[o + pa]; int ia = I[o + pa];
                float kb = K[p + pb]; int ib = I[p + pb];
                if (better(ka, ia, kb, ib)) { ov[j] = ka; oi[j] = ia; pa++; }
                else                        { ov[j] = kb; oi[j] = ib; pb++; }
            }
            #pragma unroll
            for (int j = 0; j < 10; j++) { K[o + j] = ov[j]; I[o + j] = oi[j]; }
        }
    }
    __syncwarp();
}

// merge two sorted-10 lists (smem) into ov/oi
__device__ __forceinline__ void merge2x10(const float* K1, const int* I1,
                                          const float* K2, const int* I2,
                                          float (&ov)[10], int (&oi)[10]) {
    int pa = 0, pb = 0;
    #pragma unroll
    for (int j = 0; j < 10; j++) {
        float ka = K1[pa]; int ia = I1[pa];
        float kb = K2[pb]; int ib = I2[pb];
        if (better(ka, ia, kb, ib)) { ov[j] = ka; oi[j] = ia; pa++; }
        else                        { ov[j] = kb; oi[j] = ib; pb++; }
    }
}

#define ROWS_PER_BLK 4
__global__ __launch_bounds__(256, 2) void k_row(const float* __restrict__ target) {
    int tid = threadIdx.x, warp = tid >> 5, lane = tid & 31;
    int rl = tid >> 6;                 // row within block 0..3
    int sub = tid & 63;                // 0..63 scan offset
    int row = blockIdx.x * ROWS_PER_BLK + rl;   // = b*TT + t
    int b = row >> 7, t = row & (TT-1);
    const float* tr = target + (size_t)row * 6;
    float x1 = tr[2], y1 = tr[3], x2 = tr[4], y2 = tr[5];
    int ci = (int)tr[1];
    float area_t = fmaxf(x2 - x1, 0.f) * fmaxf(y2 - y1, 0.f);

    const float2* SIrow = d_SI + b*AA;
    const float* Drow = d_D + ((size_t)(b*CC + ci)) * AA;
    const float4* Prow = d_pbox + b*AA;
    const unsigned* wrow = d_ibc + (b*4 + (t >> 5))*AA;
    unsigned tbit = 1u << (t & 31);

    float lkI[10], lkC[10]; int liI[10], liC[10];
    #pragma unroll
    for (int j = 0; j < 10; j++) {
        lkI[j] = -FLT_MAX; liI[j] = INT_MAX;
        lkC[j] = -FLT_MAX; liC[j] = INT_MAX;
    }

    for (int a = sub; a < AA; a += 64) {
        float4 pb = Prow[a];
        float2 si = SIrow[a];
        bool inb = si.y != 0.f;
        bool ibc = (wrow[a] & tbit) != 0;
        float iou, cost;
        pair_iou_cost(pb, inb, ibc, si.x, Drow[a], x1, y1, x2, y2, area_t, iou, cost);
        insert10(lkI, liI, iou, a);
        insert10(lkC, liC, -cost, a);
    }

    __shared__ float sK[256*10];
    __shared__ int   sI[256*10];
    __shared__ int   s_dk[ROWS_PER_BLK];
    float* wK = sK + warp*320;
    int*   wI = sI + warp*320;

    // phase 0: iou -> dyn_k, rowmax
    #pragma unroll
    for (int j = 0; j < 10; j++) { wK[lane*10 + j] = lkI[j]; wI[lane*10 + j] = liI[j]; }
    warp_merge10(wK, wI, lane);
    __syncthreads();
    if ((warp & 1) == 0 && lane == 0) {
        float ov[10]; int oi[10];
        merge2x10(wK, wI, wK + 320, wI + 320, ov, oi);
        float s = 0.f;
        #pragma unroll
        for (int j = 0; j < 10; j++) s += ov[j];
        int dk = (int)s;                 // truncation, matches astype(int32)
        if (dk < 1) dk = 1; if (dk > 10) dk = 10;
        s_dk[rl] = dk;
        d_rowmax[row] = ov[0];
    }
    __syncthreads();

    // phase 1: -cost -> scatter matches
    #pragma unroll
    for (int j = 0; j < 10; j++) { wK[lane*10 + j] = lkC[j]; wI[lane*10 + j] = liC[j]; }
    warp_merge10(wK, wI, lane);
    __syncthreads();
    if ((warp & 1) == 0 && lane == 0) {
        float ov[10]; int oi[10];
        merge2x10(wK, wI, wK + 320, wI + 320, ov, oi);
        int dk = s_dk[rl];
        for (int j = 0; j < dk; j++) {
            int aa = oi[j];
            if (d_inb[b*AA + aa]) {
                atomicAdd(&d_mcnt[b*AA + aa], 1);
                atomicMin(&d_mt[b*AA + aa], t);
            }
        }
    }
}

// ---------------- col pass: recompute + piou/argmin + fused loss ----------------
__global__ __launch_bounds__(256) void k_col(const float* __restrict__ target) {
    int b = blockIdx.y;
    int a = blockIdx.x * blockDim.x + threadIdx.x;
    int tid = threadIdx.x;
    __shared__ float s_x1[TT], s_y1[TT], s_x2[TT], s_y2[TT], s_ar[TT], s_inv[TT];
    __shared__ int   s_cia[TT];
    if (tid < TT) {
        const float* tb = target + ((size_t)b*TT + tid)*6;
        float X1 = tb[2], Y1 = tb[3], X2 = tb[4], Y2 = tb[5];
        s_x1[tid] = X1; s_y1[tid] = Y1; s_x2[tid] = X2; s_y2[tid] = Y2;
        s_ar[tid] = fmaxf(X2 - X1, 0.f) * fmaxf(Y2 - Y1, 0.f);
        s_cia[tid] = (b*CC + (int)tb[1]) * AA;
        s_inv[tid] = __fdividef(1.f, d_rowmax[b*TT + tid] + 1e-8f);
    }
    __syncthreads();

    float t_lbox = 0.f, t_m = 0.f, t_lobj = 0.f, t_lcls = 0.f;
    if (a < AA) {
        int ba = b*AA + a;
        float4 pb = d_pbox[ba];
        float2 si = d_SI[ba];
        bool inb = si.y != 0.f;
        float S = si.x;
        unsigned wv[4];
        #pragma unroll
        for (int ch = 0; ch < 4; ch++) wv[ch] = d_ibc[(b*4 + ch)*AA + a];

        float piou = 0.f;
        float bestc = FLT_MAX; int bestt = 0;
        #pragma unroll 4
        for (int t = 0; t < TT; t++) {
            bool ibc = (wv[t >> 5] >> (t & 31)) & 1u;
            float iou, cost;
            pair_iou_cost(pb, inb, ibc, S, d_D[(size_t)s_cia[t] + a],
                          s_x1[t], s_y1[t], s_x2[t], s_y2[t], s_ar[t], iou, cost);
            piou = fmaxf(piou, iou * s_inv[t]);
            if (cost < bestc) { bestc = cost; bestt = t; }   // first min = argmin
        }

        float objt = inb ? fminf(fmaxf(piou, 0.f), 1.f) : 0.f;
        t_lobj = bce(d_predT[(size_t)4*NN + ba], objt);

        int cnt = d_mcnt[ba];
        int tp = -1;
        if (cnt == 1) tp = d_mt[ba];
        else if (cnt > 1) tp = bestt;
        if (tp >= 0) {
            t_m = 1.f;
            float tx1 = s_x1[tp], ty1 = s_y1[tp], tx2 = s_x2[tp], ty2 = s_y2[tp];
            int ci = s_cia[tp] / AA - b*CC;
            // CIoU
            float ltx = fmaxf(pb.x, tx1), lty = fmaxf(pb.y, ty1);
            float rbx = fminf(pb.z, tx2), rby = fminf(pb.w, ty2);
            float wx = fmaxf(rbx - ltx, 0.f), wy = fmaxf(rby - lty, 0.f);
            float inter = wx * wy;
            float wp = pb.z - pb.x, hp = pb.w - pb.y;
            float wt = tx2 - tx1, ht = ty2 - ty1;
            float iou = inter / (wp*hp + wt*ht - inter + 1e-8f);
            float cw = fmaxf(pb.z, tx2) - fminf(pb.x, tx1);
            float chh = fmaxf(pb.w, ty2) - fminf(pb.y, ty1);
            float c2 = cw*cw + chh*chh + 1e-8f;
            float dx = pb.x + pb.z - (tx1 + tx2);
            float dy = pb.y + pb.w - (ty1 + ty2);
            float rho2 = (dx*dx + dy*dy) * 0.25f;
            const float k4pi2 = (float)(4.0 / (M_PI * M_PI));
            float dv = atanf(wt / (ht + 1e-8f)) - atanf(wp / (hp + 1e-8f));
            float v = k4pi2 * dv * dv;
            float alpha = v / (1.f - iou + v + 1e-8f);
            float ciou = iou - rho2 / c2 - alpha * v;
            t_lbox = 1.f - ciou;
            float s = 0.f;
            for (int c = 0; c < CC; c++)
                s += bce(d_predT[(size_t)(5 + c)*NN + ba], (c == ci) ? 1.f : 0.f);
            t_lcls = s * (1.0f / CC);
        }
    }

    // block reduction of 4 partials
    __shared__ float red[4*256];
    red[tid] = t_lbox; red[256 + tid] = t_m;
    red[512 + tid] = t_lobj; red[768 + tid] = t_lcls;
    __syncthreads();
    for (int s = 128; s > 0; s >>= 1) {
        if (tid < s) {
            red[tid]       += red[tid + s];
            red[256 + tid] += red[256 + tid + s];
            red[512 + tid] += red[512 + tid + s];
            red[768 + tid] += red[768 + tid + s];
        }
        __syncthreads();
    }
    if (tid == 0) {
        atomicAdd(&d_acc[0], (double)red[0]);
        atomicAdd(&d_acc[1], (double)red[256]);
        atomicAdd(&d_acc[2], (double)red[512]);
        atomicAdd(&d_acc[3], (double)red[768]);
    }
}

// ---------------- finalize ----------------
__global__ void k_final(float* out, int n) {
    double nm = d_acc[1];
    if (nm < 1.0) nm = 1.0;
    float lbox = (float)(0.05 * d_acc[0] / nm);
    float lobj = (float)(d_acc[2] / (double)(NN));
    float lcls = (float)(0.5 * d_acc[3] / nm);
    float loss = lbox + lobj + lcls;
    if (n > 0) out[0] = loss;
    if (n > 1) out[1] = lbox;
    if (n > 2) out[2] = lobj;
    if (n > 3) out[3] = lcls;
}

// ---------------- launch ----------------
extern "C" void kernel_launch(void* const* d_in, const int* in_sizes, int n_in,
                              void* d_out, int out_size) {
    const float *pred = nullptr, *target = nullptr, *grid = nullptr, *stridem = nullptr;
    for (int i = 0; i < n_in; i++) {
        switch (in_sizes[i]) {
            case BB*AA*85:  pred    = (const float*)d_in[i]; break;
            case BB*TT*6:   target  = (const float*)d_in[i]; break;
            case AA*2:      grid    = (const float*)d_in[i]; break;
            case AA:        stridem = (const float*)d_in[i]; break;
            default: break;
        }
    }
    if (!pred    && n_in > 0) pred    = (const float*)d_in[0];
    if (!target  && n_in > 1) target  = (const float*)d_in[1];
    if (!grid    && n_in > 2) grid    = (const float*)d_in[2];
    if (!stridem && n_in > 3) stridem = (const float*)d_in[3];
    float* out = (float*)d_out;

    k_init<<<(NN + 255)/256, 256>>>(grid, stridem);
    {
        dim3 g(3, (NN + 31)/32);
        dim3 blk(32, 8);
        k_transpose<<<g, blk>>>(pred);
    }
    {
        dim3 g((NN + 255)/256, NG);
        k_pass1<<<g, 256>>>();
    }
    {
        dim3 g((AA + 255)/256, 4, BB);
        k_flags<<<g, 256>>>(target);
    }
    k_combine<<<(NN + 255)/256, 256>>>();
    k_row<<<(BB*TT)/ROWS_PER_BLK, 256>>>(target);
    {
        dim3 g((AA + 255)/256, BB);
        k_col<<<g, 256>>>(target);
    }
    k_final<<<1, 1>>>(out, out_size);
}

// round 6
// speedup vs baseline: 3.1278x; 1.4571x over previous
#include <cuda_runtime.h>
#include <math.h>
#include <float.h>
#include <limits.h>
#include <stdint.h>

#define BB 16
#define AA 8400
#define TT 128
#define CC 80
#define NN (BB*AA)
#define NG 4          // class groups in pass1
#define CG (CC/NG)    // classes per group (20)
#define TA 1024       // anchor tile in k_row

// ---------------- scratch (static device globals; no allocation) ----------------
__device__ float d_D[(size_t)BB*CC*AA];         // (logp - log1mp), class-major
__device__ float d_Spart[(size_t)NG*NN];        // partial log1mp sums per group
__device__ float d_obj[NN];                     // obj logit (channel 4)
__device__ float2 d_SI[NN];                     // {S, in_box}
__device__ float4 d_pbox[NN];                   // pred boxes packed
__device__ float4 d_anchor[AA];                 // xc, yc, stride
__device__ unsigned char d_inb[NN];             // in_box byte
__device__ unsigned char d_any4[(size_t)4*NN];  // per-chunk any flag
__device__ unsigned int d_ibc[BB*4*AA];         // in_box&in_center bitmask, word-major
__device__ float d_rowmax[BB*TT];
__device__ int   d_mcnt[NN];
__device__ int   d_mt[NN];
__device__ double d_acc[4];                     // lbox_sum, m_sum, lobj_sum, lcls_sum

__device__ __forceinline__ float bce(float x, float t) {
    return fmaxf(x, 0.f) - x * t + __logf(1.f + __expf(-fabsf(x)));
}
// jax.lax.top_k: stable — larger value first, ties -> smaller index first
__device__ __forceinline__ bool better(float k1, int i1, float k2, int i2) {
    return (k1 > k2) || (k1 == k2 && i1 < i2);
}

// register-resident indexed top-10 insert (static indexing, no spill)
__device__ __forceinline__ void insert10(float (&lk)[10], int (&li)[10], float k, int i) {
    if (!better(k, i, lk[9], li[9])) return;
    bool p[10];
    #pragma unroll
    for (int q = 0; q < 10; q++) p[q] = better(k, i, lk[q], li[q]);
    #pragma unroll
    for (int q = 9; q >= 1; q--) {
        if (p[q]) {
            lk[q] = p[q-1] ? lk[q-1] : k;
            li[q] = p[q-1] ? li[q-1] : i;
        }
    }
    if (p[0]) { lk[0] = k; li[0] = i; }
}

// value-only top-10 insert (for iou: only values feed dyn_k / rowmax)
__device__ __forceinline__ void insert10v(float (&lk)[10], float k) {
    if (!(k > lk[9])) return;
    bool p[10];
    #pragma unroll
    for (int q = 0; q < 10; q++) p[q] = (k > lk[q]);
    #pragma unroll
    for (int q = 9; q >= 1; q--) {
        if (p[q]) lk[q] = p[q-1] ? lk[q-1] : k;
    }
    if (p[0]) lk[0] = k;
}

// shared pair iou/cost computation — used identically by row kernel and col conflict path
__device__ __forceinline__ void pair_iou_cost(
    float4 pb, bool inb, bool ibc, float S, float Dv,
    float x1, float y1, float x2, float y2, float area_t,
    float& iou_out, float& cost_out)
{
    float ltx = fmaxf(x1, pb.x), lty = fmaxf(y1, pb.y);
    float rbx = fminf(x2, pb.z), rby = fminf(y2, pb.w);
    float wx = fmaxf(rbx - ltx, 0.f), wy = fmaxf(rby - lty, 0.f);
    float inter = wx * wy;
    float area_p = fmaxf(pb.z - pb.x, 0.f) * fmaxf(pb.w - pb.y, 0.f);
    float iou = __fdividef(inter, area_t + area_p - inter + 1e-8f);
    iou = inb ? iou : 0.f;
    float iouc = -__logf(iou + 1e-8f);
    float clsc = -(S + Dv);
    float cost = fmaf(3.0f, iouc, clsc);
    if (!ibc) cost += 100000.0f;
    if (!inb) cost += 1000000000.0f;
    iou_out = iou;
    cost_out = cost;
}

// ---------------- init (+anchor fused) ----------------
__global__ void k_init(const float* __restrict__ grid, const float* __restrict__ str) {
    int i = blockIdx.x * blockDim.x + threadIdx.x;
    if (i < NN) { d_mcnt[i] = 0; d_mt[i] = INT_MAX; }
    if (i < 4) d_acc[i] = 0.0;
    if (i < AA) {
        float s = str[i];
        float4 v;
        v.x = (grid[2*i] + 0.5f) * s;
        v.y = (grid[2*i+1] + 0.5f) * s;
        v.z = s; v.w = 0.f;
        d_anchor[i] = v;
    }
}

// ---------------- pass1: smem-staged, 128 anchors x 4 class-groups per block ----------------
__global__ __launch_bounds__(512) void k_pass1(const float* __restrict__ pred) {
    __shared__ float tile[128*85];
    int i0 = blockIdx.x * 128;
    // coalesced stage of 128 pred rows (contiguous 128*85 floats)
    const float* src = pred + (size_t)i0 * 85;
    for (int j = threadIdx.x; j < 128*85; j += 512)
        tile[j] = src[j];
    __syncthreads();

    int al = threadIdx.x & 127;          // anchor within tile
    int g  = threadIdx.x >> 7;           // class group 0..3
    int i  = i0 + al;
    int b = i / AA, a = i - b*AA;
    const float* row = tile + al*85;

    if (g == 0) {
        float4 pb; pb.x = row[0]; pb.y = row[1]; pb.z = row[2]; pb.w = row[3];
        d_pbox[i] = pb;
        d_obj[i] = row[4];
    }
    float xo = row[4];
    float A0 = 1.f + __expf(-xo);
    float S = 0.f;
    size_t dbase = (size_t)b*CC*AA + a;
    int c0 = g * CG;
    #pragma unroll 5
    for (int cc = 0; cc < CG; cc++) {
        int c = c0 + cc;
        float xc = row[5 + c];
        float u  = A0 * (1.f + __expf(-xc));     // = 1/(so*sc)
        float p  = rsqrtf(u);
        float lp = fmaxf(-0.5f * __logf(u), -100.f);
        float l1 = fmaxf(__logf(1.f - p), -100.f);
        S += l1;
        d_D[dbase + (size_t)c*AA] = lp - l1;
    }
    d_Spart[(size_t)g*NN + i] = S;
}

// ---------------- flags: geometric (4-way target-chunk split) ----------------
__global__ void k_flags(const float* __restrict__ target) {
    int b = blockIdx.z, ch = blockIdx.y;
    int a = blockIdx.x * blockDim.x + threadIdx.x;
    __shared__ float st[32*6];
    for (int i = threadIdx.x; i < 32*6; i += blockDim.x)
        st[i] = target[((size_t)b*TT + ch*32)*6 + i];
    __syncthreads();
    if (a >= AA) return;
    float4 an = d_anchor[a];
    float xc = an.x, yc = an.y, r = 2.5f * an.z;
    unsigned w = 0;
    bool any = false;
    #pragma unroll 4
    for (int tt = 0; tt < 32; tt++) {
        const float* tb = st + tt*6;
        float x1 = tb[2], y1 = tb[3], x2 = tb[4], y2 = tb[5];
        float dmin = fminf(fminf(xc - x1, yc - y1), fminf(x2 - xc, y2 - yc));
        bool ib = dmin > 0.f;
        float txc = (x1 + x2) * 0.5f, tyc = (y1 + y2) * 0.5f;
        bool ic = fmaxf(fabsf(xc - txc), fabsf(yc - tyc)) < r;
        any |= (ib || ic);
        if (ib && ic) w |= (1u << tt);
    }
    d_ibc[(b*4 + ch)*AA + a] = w;
    d_any4[((size_t)ch*NN) + b*AA + a] = any ? 1 : 0;
}

// combine: in_box OR + partial-S sum
__global__ void k_combine() {
    int i = blockIdx.x * blockDim.x + threadIdx.x;
    if (i >= NN) return;
    unsigned char v = d_any4[i] | d_any4[i + (size_t)NN]
                    | d_any4[i + (size_t)2*NN] | d_any4[i + (size_t)3*NN];
    d_inb[i] = v;
    float S = 0.f;
    #pragma unroll
    for (int g = 0; g < NG; g++) S += d_Spart[(size_t)g*NN + i];
    float2 si; si.x = S; si.y = v ? 1.f : 0.f;
    d_SI[i] = si;
}

// ---------------- row pass: 8 targets/block share smem anchor tiles ----------------
__device__ __forceinline__ void warp_merge10(float* K, int* I, int lane) {
    for (int step = 1; step < 32; step <<= 1) {
        __syncwarp();
        if ((lane & (2*step - 1)) == 0) {
            int o = lane*10, p = (lane + step)*10;
            int pa = 0, pb = 0;
            float ov[10]; int oi[10];
            #pragma unroll
            for (int j = 0; j < 10; j++) {
                float ka = K[o + pa]; int ia = I[o + pa];
                float kb = K[p + pb]; int ib = I[p + pb];
                if (better(ka, ia, kb, ib)) { ov[j] = ka; oi[j] = ia; pa++; }
                else                        { ov[j] = kb; oi[j] = ib; pb++; }
            }
            #pragma unroll
            for (int j = 0; j < 10; j++) { K[o + j] = ov[j]; I[o + j] = oi[j]; }
        }
    }
    __syncwarp();
}

__device__ __forceinline__ void warp_merge10v(float* K, int lane) {
    for (int step = 1; step < 32; step <<= 1) {
        __syncwarp();
        if ((lane & (2*step - 1)) == 0) {
            int o = lane*10, p = (lane + step)*10;
            int pa = 0, pb = 0;
            float ov[10];
            #pragma unroll
            for (int j = 0; j < 10; j++) {
                float ka = K[o + pa];
                float kb = K[p + pb];
                if (ka >= kb) { ov[j] = ka; pa++; }
                else          { ov[j] = kb; pb++; }
            }
            #pragma unroll
            for (int j = 0; j < 10; j++) K[o + j] = ov[j];
        }
    }
    __syncwarp();
}

__global__ __launch_bounds__(256) void k_row(const float* __restrict__ target) {
    __shared__ __align__(16) char s_buf[TA*16 + TA*8 + TA*4];   // 28KB
    float4*   s_pb = (float4*)s_buf;
    float2*   s_si = (float2*)(s_buf + TA*16);
    unsigned* s_w  = (unsigned*)(s_buf + TA*24);

    int b  = blockIdx.x >> 4;
    int t0 = (blockIdx.x & 15) * 8;          // 8 targets, all within one 32-chunk
    int warp = threadIdx.x >> 5, lane = threadIdx.x & 31;
    int t = t0 + warp;
    int row = b*TT + t;
    const float* tr = target + (size_t)row * 6;
    float x1 = tr[2], y1 = tr[3], x2 = tr[4], y2 = tr[5];
    int ci = (int)tr[1];
    float area_t = fmaxf(x2 - x1, 0.f) * fmaxf(y2 - y1, 0.f);
    const float* Drow = d_D + ((size_t)(b*CC + ci)) * AA;
    unsigned tbit = 1u << (t & 31);
    int chunk = t >> 5;

    const float4* Pg = d_pbox + b*AA;
    const float2* Sg = d_SI + b*AA;
    const unsigned* Wg = d_ibc + (b*4 + chunk)*AA;

    float lkI[10], lkC[10]; int liC[10];
    #pragma unroll
    for (int j = 0; j < 10; j++) { lkI[j] = -FLT_MAX; lkC[j] = -FLT_MAX; liC[j] = INT_MAX; }

    for (int a0 = 0; a0 < AA; a0 += TA) {
        int cnt = min(TA, AA - a0);
        __syncthreads();
        for (int j = threadIdx.x; j < cnt; j += 256) {
            s_pb[j] = Pg[a0 + j];
            s_si[j] = Sg[a0 + j];
            s_w[j]  = Wg[a0 + j];
        }
        __syncthreads();
        #pragma unroll 2
        for (int j = lane; j < cnt; j += 32) {
            int a = a0 + j;
            float4 pb = s_pb[j];
            float2 si = s_si[j];
            bool inb = si.y != 0.f;
            bool ibc = (s_w[j] & tbit) != 0;
            float iou, cost;
            pair_iou_cost(pb, inb, ibc, si.x, Drow[a], x1, y1, x2, y2, area_t, iou, cost);
            insert10v(lkI, iou);
            insert10(lkC, liC, -cost, a);
        }
    }
    __syncthreads();

    // merge buffers alias the tile smem (tiles fully consumed)
    float* mK = (float*)s_buf + warp*320;                 // 8*320*4 = 10240 B
    int*   mI = (int*)(s_buf + 10240) + warp*320;         // next 10240 B

    // phase 0: iou values -> dyn_k, rowmax (per-warp independent)
    #pragma unroll
    for (int j = 0; j < 10; j++) mK[lane*10 + j] = lkI[j];
    warp_merge10v(mK, lane);
    int dk = 0;
    if (lane == 0) {
        float s = 0.f;
        #pragma unroll
        for (int j = 0; j < 10; j++) s += mK[j];
        dk = (int)s;                 // truncation, matches astype(int32)
        if (dk < 1) dk = 1; if (dk > 10) dk = 10;
        d_rowmax[row] = mK[0];
    }
    __syncwarp();

    // phase 1: -cost with indices -> scatter matches
    #pragma unroll
    for (int j = 0; j < 10; j++) { mK[lane*10 + j] = lkC[j]; mI[lane*10 + j] = liC[j]; }
    warp_merge10(mK, mI, lane);
    if (lane == 0) {
        for (int j = 0; j < dk; j++) {
            int aa = mI[j];
            if (d_inb[b*AA + aa]) {
                atomicAdd(&d_mcnt[b*AA + aa], 1);
                atomicMin(&d_mt[b*AA + aa], t);
            }
        }
    }
}

// ---------------- col pass: iou-only piou + rare conflict argmin + fused loss ----------------
__global__ __launch_bounds__(256) void k_col(const float* __restrict__ pred,
                                             const float* __restrict__ target) {
    int b = blockIdx.y;
    int a = blockIdx.x * blockDim.x + threadIdx.x;
    int tid = threadIdx.x;
    __shared__ float4 s_tb[TT];
    __shared__ float s_ar[TT], s_inv[TT];
    __shared__ int   s_cia[TT];
    if (tid < TT) {
        const float* tb = target + ((size_t)b*TT + tid)*6;
        float X1 = tb[2], Y1 = tb[3], X2 = tb[4], Y2 = tb[5];
        float4 v; v.x = X1; v.y = Y1; v.z = X2; v.w = Y2;
        s_tb[tid] = v;
        s_ar[tid] = fmaxf(X2 - X1, 0.f) * fmaxf(Y2 - Y1, 0.f);
        s_cia[tid] = (b*CC + (int)tb[1]) * AA;
        s_inv[tid] = __fdividef(1.f, d_rowmax[b*TT + tid] + 1e-8f);
    }
    __syncthreads();

    float t_lbox = 0.f, t_m = 0.f, t_lobj = 0.f, t_lcls = 0.f;
    if (a < AA) {
        int ba = b*AA + a;
        float4 pb = d_pbox[ba];
        float2 si = d_SI[ba];
        bool inb = si.y != 0.f;
        float S = si.x;

        // main loop: iou only (no D loads, no logs)
        float piou = 0.f;
        if (inb) {
            float area_p = fmaxf(pb.z - pb.x, 0.f) * fmaxf(pb.w - pb.y, 0.f);
            #pragma unroll 8
            for (int t = 0; t < TT; t++) {
                float4 tb = s_tb[t];
                float ltx = fmaxf(tb.x, pb.x), lty = fmaxf(tb.y, pb.y);
                float rbx = fminf(tb.z, pb.z), rby = fminf(tb.w, pb.w);
                float wx = fmaxf(rbx - ltx, 0.f), wy = fmaxf(rby - lty, 0.f);
                float inter = wx * wy;
                float iou = __fdividef(inter, s_ar[t] + area_p - inter + 1e-8f);
                piou = fmaxf(piou, iou * s_inv[t]);
            }
        }
        float objt = inb ? fminf(fmaxf(piou, 0.f), 1.f) : 0.f;
        t_lobj = bce(d_obj[ba], objt);

        int cnt = d_mcnt[ba];
        int tp = -1;
        if (cnt == 1) tp = d_mt[ba];
        else if (cnt > 1) {
            // rare conflict: exact argmin of cost (bitwise same as k_row's cost)
            unsigned wv[4];
            #pragma unroll
            for (int ch = 0; ch < 4; ch++) wv[ch] = d_ibc[(b*4 + ch)*AA + a];
            float bestc = FLT_MAX; int bestt = 0;
            for (int t = 0; t < TT; t++) {
                bool ibc = (wv[t >> 5] >> (t & 31)) & 1u;
                float4 tb = s_tb[t];
                float iou, cost;
                pair_iou_cost(pb, inb, ibc, S, d_D[(size_t)s_cia[t] + a],
                              tb.x, tb.y, tb.z, tb.w, s_ar[t], iou, cost);
                if (cost < bestc) { bestc = cost; bestt = t; }   // first min = argmin
            }
            tp = bestt;
        }
        if (tp >= 0) {
            t_m = 1.f;
            float4 tb = s_tb[tp];
            float tx1 = tb.x, ty1 = tb.y, tx2 = tb.z, ty2 = tb.w;
            int ci = s_cia[tp] / AA - b*CC;
            // CIoU
            float ltx = fmaxf(pb.x, tx1), lty = fmaxf(pb.y, ty1);
            float rbx = fminf(pb.z, tx2), rby = fminf(pb.w, ty2);
            float wx = fmaxf(rbx - ltx, 0.f), wy = fmaxf(rby - lty, 0.f);
            float inter = wx * wy;
            float wp = pb.z - pb.x, hp = pb.w - pb.y;
            float wt = tx2 - tx1, ht = ty2 - ty1;
            float iou = inter / (wp*hp + wt*ht - inter + 1e-8f);
            float cw = fmaxf(pb.z, tx2) - fminf(pb.x, tx1);
            float chh = fmaxf(pb.w, ty2) - fminf(pb.y, ty1);
            float c2 = cw*cw + chh*chh + 1e-8f;
            float dx = pb.x + pb.z - (tx1 + tx2);
            float dy = pb.y + pb.w - (ty1 + ty2);
            float rho2 = (dx*dx + dy*dy) * 0.25f;
            const float k4pi2 = (float)(4.0 / (M_PI * M_PI));
            float dv = atanf(wt / (ht + 1e-8f)) - atanf(wp / (hp + 1e-8f));
            float v = k4pi2 * dv * dv;
            float alpha = v / (1.f - iou + v + 1e-8f);
            float ciou = iou - rho2 / c2 - alpha * v;
            t_lbox = 1.f - ciou;
            // cls BCE from original pred row (matched anchors only, ~2%)
            const float* prow = pred + (size_t)ba * 85;
            float s = 0.f;
            for (int c = 0; c < CC; c++)
                s += bce(prow[5 + c], (c == ci) ? 1.f : 0.f);
            t_lcls = s * (1.0f / CC);
        }
    }

    // block reduction of 4 partials
    __shared__ float red[4*256];
    red[tid] = t_lbox; red[256 + tid] = t_m;
    red[512 + tid] = t_lobj; red[768 + tid] = t_lcls;
    __syncthreads();
    for (int s = 128; s > 0; s >>= 1) {
        if (tid < s) {
            red[tid]       += red[tid + s];
            red[256 + tid] += red[256 + tid + s];
            red[512 + tid] += red[512 + tid + s];
            red[768 + tid] += red[768 + tid + s];
        }
        __syncthreads();
    }
    if (tid == 0) {
        atomicAdd(&d_acc[0], (double)red[0]);
        atomicAdd(&d_acc[1], (double)red[256]);
        atomicAdd(&d_acc[2], (double)red[512]);
        atomicAdd(&d_acc[3], (double)red[768]);
    }
}

// ---------------- finalize ----------------
__global__ void k_final(float* out, int n) {
    double nm = d_acc[1];
    if (nm < 1.0) nm = 1.0;
    float lbox = (float)(0.05 * d_acc[0] / nm);
    float lobj = (float)(d_acc[2] / (double)(NN));
    float lcls = (float)(0.5 * d_acc[3] / nm);
    float loss = lbox + lobj + lcls;
    if (n > 0) out[0] = loss;
    if (n > 1) out[1] = lbox;
    if (n > 2) out[2] = lobj;
    if (n > 3) out[3] = lcls;
}

// ---------------- launch ----------------
extern "C" void kernel_launch(void* const* d_in, const int* in_sizes, int n_in,
                              void* d_out, int out_size) {
    const float *pred = nullptr, *target = nullptr, *grid = nullptr, *stridem = nullptr;
    for (int i = 0; i < n_in; i++) {
        switch (in_sizes[i]) {
            case BB*AA*85:  pred    = (const float*)d_in[i]; break;
            case BB*TT*6:   target  = (const float*)d_in[i]; break;
            case AA*2:      grid    = (const float*)d_in[i]; break;
            case AA:        stridem = (const float*)d_in[i]; break;
            default: break;
        }
    }
    if (!pred    && n_in > 0) pred    = (const float*)d_in[0];
    if (!target  && n_in > 1) target  = (const float*)d_in[1];
    if (!grid    && n_in > 2) grid    = (const float*)d_in[2];
    if (!stridem && n_in > 3) stridem = (const float*)d_in[3];
    float* out = (float*)d_out;

    k_init<<<(NN + 255)/256, 256>>>(grid, stridem);
    k_pass1<<<NN/128, 512>>>(pred);
    {
        dim3 g((AA + 255)/256, 4, BB);
        k_flags<<<g, 256>>>(target);
    }
    k_combine<<<(NN + 255)/256, 256>>>();
    k_row<<<BB*16, 256>>>(target);
    {
        dim3 g((AA + 255)/256, BB);
        k_col<<<g, 256>>>(pred, target);
    }
    k_final<<<1, 1>>>(out, out_size);
}